// round 1
// baseline (speedup 1.0000x reference)
#include <cuda_runtime.h>
#include <cuda_bf16.h>
#include <math.h>

#define DIMV    2048
#define NHEADS  16
#define HD      128
#define HIDDEN  8192
#define BATCH   2
#define SEQ     2048
#define MTOT    (BATCH*SEQ)      // 4096 rows
#define EPSV    1e-6f

// ---------------- scratch (device globals; no allocation allowed) ----------------
__device__ float g_xn[MTOT*DIMV];    // rmsnorm output (reused for hn)
__device__ float g_q [MTOT*DIMV];
__device__ float g_k [MTOT*DIMV];
__device__ float g_v [MTOT*DIMV];
__device__ float g_at[MTOT*DIMV];    // attention output
__device__ float g_h [MTOT*DIMV];    // x + attn@wo
__device__ float g_h1[MTOT*HIDDEN];
__device__ float g_h3[MTOT*HIDDEN];

// ---------------- RMSNorm ----------------
__global__ __launch_bounds__(256) void rmsnorm_kernel(
    const float* __restrict__ x, const float* __restrict__ w, float* __restrict__ y)
{
    int row = blockIdx.x;
    const float* xr = x + (size_t)row * DIMV;
    float ss = 0.f;
    for (int i = threadIdx.x * 4; i < DIMV; i += blockDim.x * 4) {
        float4 v = *(const float4*)(xr + i);
        ss += v.x*v.x + v.y*v.y + v.z*v.z + v.w*v.w;
    }
    // block reduce
    __shared__ float red[8];
    for (int o = 16; o > 0; o >>= 1) ss += __shfl_down_sync(0xffffffffu, ss, o);
    int warp = threadIdx.x >> 5, lane = threadIdx.x & 31;
    if (lane == 0) red[warp] = ss;
    __syncthreads();
    if (warp == 0) {
        float t = (lane < 8) ? red[lane] : 0.f;
        for (int o = 4; o > 0; o >>= 1) t += __shfl_down_sync(0xffffffffu, t, o);
        if (lane == 0) red[0] = t;
    }
    __syncthreads();
    float r = rsqrtf(red[0] / (float)DIMV + EPSV);
    float* yr = y + (size_t)row * DIMV;
    for (int i = threadIdx.x * 4; i < DIMV; i += blockDim.x * 4) {
        float4 v = *(const float4*)(xr + i);
        float4 ww = *(const float4*)(w + i);
        float4 o4;
        o4.x = v.x * r * ww.x; o4.y = v.y * r * ww.y;
        o4.z = v.z * r * ww.z; o4.w = v.w * r * ww.w;
        *(float4*)(yr + i) = o4;
    }
}

// ---------------- GEMM: C[M,N] = A[M,K] @ B[K,N] (+ R) ----------------
// 128x128 block tile, BK=8, 256 threads, 8x8 per-thread micro-tile.
__global__ __launch_bounds__(256) void gemm_kernel(
    const float* __restrict__ A, const float* __restrict__ B,
    const float* __restrict__ R, float* __restrict__ C,
    int Mn, int Nn, int Kn)
{
    __shared__ float As[8][128];
    __shared__ float Bs[8][128];
    const int bm = blockIdx.y * 128, bn = blockIdx.x * 128;
    const int tid = threadIdx.x;
    const int tx = tid & 15, ty = tid >> 4;

    float acc[8][8];
    #pragma unroll
    for (int i = 0; i < 8; i++)
        #pragma unroll
        for (int j = 0; j < 8; j++) acc[i][j] = 0.f;

    const int arow = tid >> 1, acol = (tid & 1) * 4;   // A tile 128x8
    const int brow = tid >> 5, bcol = (tid & 31) * 4;  // B tile 8x128
    const float* Aptr = A + (size_t)(bm + arow) * Kn + acol;
    const float* Bptr = B + (size_t)brow * Nn + bn + bcol;

    for (int k0 = 0; k0 < Kn; k0 += 8) {
        float4 av = *(const float4*)(Aptr + k0);
        float4 bv = *(const float4*)(Bptr + (size_t)k0 * Nn);
        As[acol + 0][arow] = av.x;
        As[acol + 1][arow] = av.y;
        As[acol + 2][arow] = av.z;
        As[acol + 3][arow] = av.w;
        *(float4*)&Bs[brow][bcol] = bv;
        __syncthreads();
        #pragma unroll
        for (int kk = 0; kk < 8; kk++) {
            float af[8], bf[8];
            *(float4*)(af)     = *(const float4*)&As[kk][ty * 8];
            *(float4*)(af + 4) = *(const float4*)&As[kk][ty * 8 + 4];
            *(float4*)(bf)     = *(const float4*)&Bs[kk][tx * 8];
            *(float4*)(bf + 4) = *(const float4*)&Bs[kk][tx * 8 + 4];
            #pragma unroll
            for (int i = 0; i < 8; i++)
                #pragma unroll
                for (int j = 0; j < 8; j++)
                    acc[i][j] = fmaf(af[i], bf[j], acc[i][j]);
        }
        __syncthreads();
    }

    #pragma unroll
    for (int i = 0; i < 8; i++) {
        int row = bm + ty * 8 + i;
        size_t base = (size_t)row * Nn + bn + tx * 8;
        if (R) {
            float4 r1 = *(const float4*)(R + base);
            float4 r2 = *(const float4*)(R + base + 4);
            acc[i][0] += r1.x; acc[i][1] += r1.y; acc[i][2] += r1.z; acc[i][3] += r1.w;
            acc[i][4] += r2.x; acc[i][5] += r2.y; acc[i][6] += r2.z; acc[i][7] += r2.w;
        }
        float4 o1 = make_float4(acc[i][0], acc[i][1], acc[i][2], acc[i][3]);
        float4 o2 = make_float4(acc[i][4], acc[i][5], acc[i][6], acc[i][7]);
        *(float4*)(C + base)     = o1;
        *(float4*)(C + base + 4) = o2;
    }
}

// ---------------- RoPE (applies to q and k in-place) ----------------
__global__ __launch_bounds__(256) void rope_kernel(
    float* __restrict__ q, float* __restrict__ k,
    const float* __restrict__ cs, const float* __restrict__ sn)
{
    int p = blockIdx.x * blockDim.x + threadIdx.x;     // pair index
    const int npairs = MTOT * (DIMV / 2);
    if (p >= npairs) return;
    int row = p / (DIMV / 2);
    int rem = p - row * (DIMV / 2);                    // h*64 + i
    int i = rem & 63;
    int s = row & (SEQ - 1);
    float c = cs[s * 64 + i];
    float si = sn[s * 64 + i];
    size_t base = (size_t)row * DIMV + 2 * rem;
    float a = q[base], b = q[base + 1];
    q[base]     = a * c - b * si;
    q[base + 1] = a * si + b * c;
    a = k[base]; b = k[base + 1];
    k[base]     = a * c - b * si;
    k[base + 1] = a * si + b * c;
}

// ---------------- Flash attention (causal), 64x64 tiles, fp32 ----------------
// grid: (S/64, B*H). block: 256 threads. O accumulators in registers (4x8/thread).
__global__ __launch_bounds__(256) void attn_kernel(
    const float* __restrict__ Q, const float* __restrict__ K,
    const float* __restrict__ V, float* __restrict__ O)
{
    extern __shared__ float sm[];
    float* Qt = sm;               // [128][64] (d-major)
    float* Kt = Qt + HD * 64;     // [128][64]
    float* Vs = Kt + HD * 64;     // [64][132] (row-major, padded)
    float* Ps = Vs + 64 * 132;    // [64][65]
    float* mrow = Ps + 64 * 65;
    float* lrow = mrow + 64;
    float* arow = lrow + 64;

    const int qt = blockIdx.x, bh = blockIdx.y;
    const int b = bh >> 4, h = bh & 15;
    const int tid = threadIdx.x;
    const int tx = tid & 15, ty = tid >> 4;
    const int q0 = qt * 64;
    const size_t headoff = (size_t)h * HD;
    const float scale = 0.08838834764831845f;  // 1/sqrt(128)

    // load Q tile transposed
    {
        int r = tid & 63, c0 = (tid >> 6) * 32;
        const float* src = Q + (size_t)(b * SEQ + q0 + r) * DIMV + headoff + c0;
        #pragma unroll
        for (int i = 0; i < 8; i++) {
            float4 v = *(const float4*)(src + 4 * i);
            int d = c0 + 4 * i;
            Qt[(d + 0) * 64 + r] = v.x;
            Qt[(d + 1) * 64 + r] = v.y;
            Qt[(d + 2) * 64 + r] = v.z;
            Qt[(d + 3) * 64 + r] = v.w;
        }
    }
    if (tid < 64) { mrow[tid] = -INFINITY; lrow[tid] = 0.f; }

    float o[4][8];
    #pragma unroll
    for (int i = 0; i < 4; i++)
        #pragma unroll
        for (int j = 0; j < 8; j++) o[i][j] = 0.f;

    for (int kt = 0; kt <= qt; kt++) {
        int k0 = kt * 64;
        __syncthreads();  // smem reuse fence (also covers Q load / m,l init)
        {
            int r = tid & 63, c0 = (tid >> 6) * 32;
            const float* ksrc = K + (size_t)(b * SEQ + k0 + r) * DIMV + headoff + c0;
            const float* vsrc = V + (size_t)(b * SEQ + k0 + r) * DIMV + headoff + c0;
            #pragma unroll
            for (int i = 0; i < 8; i++) {
                float4 kv = *(const float4*)(ksrc + 4 * i);
                int d = c0 + 4 * i;
                Kt[(d + 0) * 64 + r] = kv.x;
                Kt[(d + 1) * 64 + r] = kv.y;
                Kt[(d + 2) * 64 + r] = kv.z;
                Kt[(d + 3) * 64 + r] = kv.w;
                float4 vv = *(const float4*)(vsrc + 4 * i);
                *(float4*)&Vs[r * 132 + c0 + 4 * i] = vv;
            }
        }
        __syncthreads();

        // S = Q K^T (64x64), each thread 4x4
        float sacc[4][4];
        #pragma unroll
        for (int i = 0; i < 4; i++)
            #pragma unroll
            for (int j = 0; j < 4; j++) sacc[i][j] = 0.f;
        for (int d = 0; d < HD; d++) {
            float qf[4], kf[4];
            *(float4*)qf = *(const float4*)&Qt[d * 64 + ty * 4];
            *(float4*)kf = *(const float4*)&Kt[d * 64 + tx * 4];
            #pragma unroll
            for (int i = 0; i < 4; i++)
                #pragma unroll
                for (int j = 0; j < 4; j++)
                    sacc[i][j] = fmaf(qf[i], kf[j], sacc[i][j]);
        }
        #pragma unroll
        for (int i = 0; i < 4; i++)
            #pragma unroll
            for (int j = 0; j < 4; j++)
                Ps[(ty * 4 + i) * 65 + tx * 4 + j] = sacc[i][j] * scale;
        __syncthreads();

        // online softmax per row
        if (tid < 64) {
            int r = tid;
            int kvalid = (kt == qt) ? (r + 1) : 64;  // causal
            float mprev = mrow[r];
            float mx = mprev;
            float* prow = Ps + r * 65;
            for (int j = 0; j < kvalid; j++) mx = fmaxf(mx, prow[j]);
            float sum = 0.f;
            for (int j = 0; j < 64; j++) {
                float pv = (j < kvalid) ? __expf(prow[j] - mx) : 0.f;
                prow[j] = pv;
                sum += pv;
            }
            float alpha = __expf(mprev - mx);
            lrow[r] = lrow[r] * alpha + sum;
            mrow[r] = mx;
            arow[r] = alpha;
        }
        __syncthreads();

        // O = O*alpha + P @ V
        float al[4];
        #pragma unroll
        for (int i = 0; i < 4; i++) al[i] = arow[ty * 4 + i];
        #pragma unroll
        for (int i = 0; i < 4; i++)
            #pragma unroll
            for (int j = 0; j < 8; j++) o[i][j] *= al[i];
        for (int jj = 0; jj < 64; jj++) {
            float vf[8];
            *(float4*)(vf)     = *(const float4*)&Vs[jj * 132 + tx * 8];
            *(float4*)(vf + 4) = *(const float4*)&Vs[jj * 132 + tx * 8 + 4];
            float pf[4];
            #pragma unroll
            for (int i = 0; i < 4; i++) pf[i] = Ps[(ty * 4 + i) * 65 + jj];
            #pragma unroll
            for (int i = 0; i < 4; i++)
                #pragma unroll
                for (int j = 0; j < 8; j++)
                    o[i][j] = fmaf(pf[i], vf[j], o[i][j]);
        }
    }

    float linv[4];
    #pragma unroll
    for (int i = 0; i < 4; i++) linv[i] = 1.f / lrow[ty * 4 + i];
    #pragma unroll
    for (int i = 0; i < 4; i++) {
        float* dst = O + (size_t)(b * SEQ + q0 + ty * 4 + i) * DIMV + headoff + tx * 8;
        float4 o1 = make_float4(o[i][0] * linv[i], o[i][1] * linv[i],
                                o[i][2] * linv[i], o[i][3] * linv[i]);
        float4 o2 = make_float4(o[i][4] * linv[i], o[i][5] * linv[i],
                                o[i][6] * linv[i], o[i][7] * linv[i]);
        *(float4*)(dst)     = o1;
        *(float4*)(dst + 4) = o2;
    }
}

// ---------------- silu(h1) * h3 -> h1 ----------------
__global__ __launch_bounds__(256) void silu_mul_kernel(
    float* __restrict__ h1, const float* __restrict__ h3, int n)
{
    int i = blockIdx.x * blockDim.x + threadIdx.x;
    if (i < n) {
        float a = h1[i];
        float g = a / (1.f + __expf(-a));
        h1[i] = g * h3[i];
    }
}

// ---------------- launch ----------------
extern "C" void kernel_launch(void* const* d_in, const int* in_sizes, int n_in,
                              void* d_out, int out_size)
{
    const float* x    = (const float*)d_in[0];
    const float* fcos = (const float*)d_in[1];
    const float* fsin = (const float*)d_in[2];
    // d_in[3] = mask (unused; causal applied directly)
    const float* wq   = (const float*)d_in[4];
    const float* wk   = (const float*)d_in[5];
    const float* wv   = (const float*)d_in[6];
    const float* wo   = (const float*)d_in[7];
    const float* w1   = (const float*)d_in[8];
    const float* w2   = (const float*)d_in[9];
    const float* w3   = (const float*)d_in[10];
    const float* anw  = (const float*)d_in[11];
    const float* fnw  = (const float*)d_in[12];
    float* out = (float*)d_out;

    float *xn, *q, *k, *v, *at, *h, *h1, *h3;
    cudaGetSymbolAddress((void**)&xn, g_xn);
    cudaGetSymbolAddress((void**)&q,  g_q);
    cudaGetSymbolAddress((void**)&k,  g_k);
    cudaGetSymbolAddress((void**)&v,  g_v);
    cudaGetSymbolAddress((void**)&at, g_at);
    cudaGetSymbolAddress((void**)&h,  g_h);
    cudaGetSymbolAddress((void**)&h1, g_h1);
    cudaGetSymbolAddress((void**)&h3, g_h3);

    const int attn_smem = (HD * 64 * 2 + 64 * 132 + 64 * 65 + 192) * (int)sizeof(float);
    cudaFuncSetAttribute(attn_kernel, cudaFuncAttributeMaxDynamicSharedMemorySize, attn_smem);

    // 1. xn = rmsnorm(x, attn_norm_w)
    rmsnorm_kernel<<<MTOT, 256>>>(x, anw, xn);

    // 2-4. q/k/v = xn @ wq/wk/wv
    dim3 gqkv(DIMV / 128, MTOT / 128);
    gemm_kernel<<<gqkv, 256>>>(xn, wq, nullptr, q, MTOT, DIMV, DIMV);
    gemm_kernel<<<gqkv, 256>>>(xn, wk, nullptr, k, MTOT, DIMV, DIMV);
    gemm_kernel<<<gqkv, 256>>>(xn, wv, nullptr, v, MTOT, DIMV, DIMV);

    // 5. RoPE on q,k
    {
        int npairs = MTOT * (DIMV / 2);
        rope_kernel<<<(npairs + 255) / 256, 256>>>(q, k, fcos, fsin);
    }

    // 6. causal attention
    attn_kernel<<<dim3(SEQ / 64, BATCH * NHEADS), 256, attn_smem>>>(q, k, v, at);

    // 7. h = x + at @ wo
    gemm_kernel<<<gqkv, 256>>>(at, wo, x, h, MTOT, DIMV, DIMV);

    // 8. hn = rmsnorm(h, ffn_norm_w)   (reuse xn buffer)
    rmsnorm_kernel<<<MTOT, 256>>>(h, fnw, xn);

    // 9-10. h1 = hn @ w1 ; h3 = hn @ w3
    dim3 gffn(HIDDEN / 128, MTOT / 128);
    gemm_kernel<<<gffn, 256>>>(xn, w1, nullptr, h1, MTOT, HIDDEN, DIMV);
    gemm_kernel<<<gffn, 256>>>(xn, w3, nullptr, h3, MTOT, HIDDEN, DIMV);

    // 11. h1 = silu(h1) * h3
    {
        int n = MTOT * HIDDEN;
        silu_mul_kernel<<<(n + 255) / 256, 256>>>(h1, h3, n);
    }

    // 12. out = h + h1 @ w2
    gemm_kernel<<<gqkv, 256>>>(h1, w2, h, out, MTOT, DIMV, HIDDEN);
}

// round 3
// speedup vs baseline: 3.6976x; 3.6976x over previous
#include <cuda_runtime.h>
#include <cuda_fp16.h>
#include <math.h>
#include <stdint.h>

#define DIMV    2048
#define NHEADS  16
#define HD      128
#define HIDDEN  8192
#define BATCH   2
#define SEQ     2048
#define MTOT    (BATCH*SEQ)      // 4096 rows
#define EPSV    1e-6f

// ---------------- scratch (device globals; no allocation allowed) ----------------
__device__ __half g_xnh[MTOT*DIMV];    // rmsnorm output, half (reused for hn)
__device__ float  g_q  [MTOT*DIMV];
__device__ float  g_k  [MTOT*DIMV];
__device__ float  g_v  [MTOT*DIMV];
__device__ __half g_ath[MTOT*DIMV];    // attention output, half
__device__ float  g_h  [MTOT*DIMV];    // x + attn@wo
__device__ float  g_h1 [MTOT*HIDDEN];
__device__ float  g_h3 [MTOT*HIDDEN];
__device__ __half g_g1h[MTOT*HIDDEN];  // silu(h1)*h3 in half
// transposed half weights ([N][K], K-contiguous)
__device__ __half g_wqT[DIMV*DIMV];
__device__ __half g_wkT[DIMV*DIMV];
__device__ __half g_wvT[DIMV*DIMV];
__device__ __half g_woT[DIMV*DIMV];
__device__ __half g_w1T[HIDDEN*DIMV];
__device__ __half g_w3T[HIDDEN*DIMV];
__device__ __half g_w2T[DIMV*HIDDEN];

__device__ __forceinline__ uint32_t smem_u32(const void* p) {
    uint32_t a;
    asm("{ .reg .u64 t; cvta.to.shared.u64 t, %1; cvt.u32.u64 %0, t; }" : "=r"(a) : "l"(p));
    return a;
}

// ---------------- RMSNorm (fp32 in, half out) ----------------
__global__ __launch_bounds__(256) void rmsnorm_kernel(
    const float* __restrict__ x, const float* __restrict__ w, __half* __restrict__ y)
{
    int row = blockIdx.x;
    const float* xr = x + (size_t)row * DIMV;
    float ss = 0.f;
    for (int i = threadIdx.x * 4; i < DIMV; i += blockDim.x * 4) {
        float4 v = *(const float4*)(xr + i);
        ss += v.x*v.x + v.y*v.y + v.z*v.z + v.w*v.w;
    }
    __shared__ float red[8];
    for (int o = 16; o > 0; o >>= 1) ss += __shfl_down_sync(0xffffffffu, ss, o);
    int warp = threadIdx.x >> 5, lane = threadIdx.x & 31;
    if (lane == 0) red[warp] = ss;
    __syncthreads();
    if (warp == 0) {
        float t = (lane < 8) ? red[lane] : 0.f;
        for (int o = 4; o > 0; o >>= 1) t += __shfl_down_sync(0xffffffffu, t, o);
        if (lane == 0) red[0] = t;
    }
    __syncthreads();
    float r = rsqrtf(red[0] / (float)DIMV + EPSV);
    __half* yr = y + (size_t)row * DIMV;
    for (int i = threadIdx.x * 4; i < DIMV; i += blockDim.x * 4) {
        float4 v = *(const float4*)(xr + i);
        float4 ww = *(const float4*)(w + i);
        __half2 h0 = __floats2half2_rn(v.x * r * ww.x, v.y * r * ww.y);
        __half2 h1 = __floats2half2_rn(v.z * r * ww.z, v.w * r * ww.w);
        *(__half2*)(yr + i)     = h0;
        *(__half2*)(yr + i + 2) = h1;
    }
}

// ---------------- transpose + fp32->half: src [R, C] -> dst [C, R] ----------------
__global__ __launch_bounds__(256) void transpose_h_kernel(
    const float* __restrict__ src, __half* __restrict__ dst, int R, int C)
{
    __shared__ float t[32][33];
    int bx = blockIdx.x * 32, by = blockIdx.y * 32;
    #pragma unroll
    for (int i = threadIdx.y; i < 32; i += 8)
        t[i][threadIdx.x] = src[(size_t)(by + i) * C + bx + threadIdx.x];
    __syncthreads();
    #pragma unroll
    for (int i = threadIdx.y; i < 32; i += 8)
        dst[(size_t)(bx + i) * R + by + threadIdx.x] = __float2half(t[threadIdx.x][i]);
}

// ---------------- HMMA fp16 GEMM: C[M,N] = A[M,K] @ Bt[N,K]^T (+R) ----------------
// 128x128 CTA tile, BK=32, 256 threads (8 warps, 2x4), warp tile 64x32.
#define GBM 128
#define GBN 128
#define GBK 32
#define APAD 40   // halves per smem row (80B -> conflict-free ldmatrix)
#define TILE_H (128*APAD)

__global__ __launch_bounds__(256) void gemm_hmma(
    const __half* __restrict__ A, const __half* __restrict__ Bt,
    const float* __restrict__ R, float* __restrict__ C,
    int Mn, int Nn, int Kn)
{
    extern __shared__ __half hs[];
    __half* As = hs;               // [2][128][APAD]
    __half* Bs = hs + 2 * TILE_H;  // [2][128][APAD]
    const int tid = threadIdx.x;
    const int lane = tid & 31, wid = tid >> 5;
    const int wm = wid >> 2, wn = wid & 3;
    const int bm = blockIdx.y * GBM, bn = blockIdx.x * GBN;

    float acc[4][4][4];
    #pragma unroll
    for (int i = 0; i < 4; i++)
        #pragma unroll
        for (int j = 0; j < 4; j++)
            #pragma unroll
            for (int q = 0; q < 4; q++) acc[i][j][q] = 0.f;

    const __half* Ag = A + (size_t)bm * Kn;
    const __half* Bg = Bt + (size_t)bn * Kn;
    const int r0 = tid >> 2, c0 = (tid & 3) * 8;          // p=0 chunk
    const int r1 = (tid + 256) >> 2;                      // p=1 chunk (same c0)
    const uint32_t sA0 = smem_u32(As), sB0 = smem_u32(Bs);

    const int NC = Kn / GBK;

#define ISSUE(stage, c)                                                          \
    {                                                                            \
        int kb = (c) * GBK;                                                      \
        uint32_t sA = sA0 + (stage) * TILE_H * 2;                                \
        uint32_t sB = sB0 + (stage) * TILE_H * 2;                                \
        const __half* ga0 = Ag + (size_t)r0 * Kn + kb + c0;                      \
        const __half* gb0 = Bg + (size_t)r0 * Kn + kb + c0;                      \
        const __half* ga1 = Ag + (size_t)r1 * Kn + kb + c0;                      \
        const __half* gb1 = Bg + (size_t)r1 * Kn + kb + c0;                      \
        asm volatile("cp.async.cg.shared.global [%0], [%1], 16;"                 \
                     :: "r"(sA + (r0 * APAD + c0) * 2), "l"(ga0));               \
        asm volatile("cp.async.cg.shared.global [%0], [%1], 16;"                 \
                     :: "r"(sB + (r0 * APAD + c0) * 2), "l"(gb0));               \
        asm volatile("cp.async.cg.shared.global [%0], [%1], 16;"                 \
                     :: "r"(sA + (r1 * APAD + c0) * 2), "l"(ga1));               \
        asm volatile("cp.async.cg.shared.global [%0], [%1], 16;"                 \
                     :: "r"(sB + (r1 * APAD + c0) * 2), "l"(gb1));               \
        asm volatile("cp.async.commit_group;" ::: "memory");                     \
    }

    ISSUE(0, 0);
    if (NC > 1) ISSUE(1, 1);

    for (int c = 0; c < NC; c++) {
        const int s = c & 1;
        asm volatile("cp.async.wait_group 1;" ::: "memory");
        __syncthreads();
        const uint32_t aBase = sA0 + s * TILE_H * 2;
        const uint32_t bBase = sB0 + s * TILE_H * 2;
        #pragma unroll
        for (int kk = 0; kk < 2; kk++) {
            uint32_t afr[4][4], bfr[4][2];
            #pragma unroll
            for (int mi = 0; mi < 4; mi++) {
                int row = wm * 64 + mi * 16 + (lane & 15);
                int col = kk * 16 + (lane >> 4) * 8;
                asm volatile("ldmatrix.sync.aligned.m8n8.x4.shared.b16 {%0,%1,%2,%3}, [%4];"
                    : "=r"(afr[mi][0]), "=r"(afr[mi][1]), "=r"(afr[mi][2]), "=r"(afr[mi][3])
                    : "r"(aBase + (row * APAD + col) * 2));
            }
            #pragma unroll
            for (int ni = 0; ni < 4; ni++) {
                int row = wn * 32 + ni * 8 + (lane & 7);
                int col = kk * 16 + ((lane >> 3) & 1) * 8;
                asm volatile("ldmatrix.sync.aligned.m8n8.x2.shared.b16 {%0,%1}, [%2];"
                    : "=r"(bfr[ni][0]), "=r"(bfr[ni][1])
                    : "r"(bBase + (row * APAD + col) * 2));
            }
            #pragma unroll
            for (int mi = 0; mi < 4; mi++)
                #pragma unroll
                for (int ni = 0; ni < 4; ni++)
                    asm volatile(
                        "mma.sync.aligned.m16n8k16.row.col.f32.f16.f16.f32 "
                        "{%0,%1,%2,%3}, {%4,%5,%6,%7}, {%8,%9}, {%0,%1,%2,%3};"
                        : "+f"(acc[mi][ni][0]), "+f"(acc[mi][ni][1]),
                          "+f"(acc[mi][ni][2]), "+f"(acc[mi][ni][3])
                        : "r"(afr[mi][0]), "r"(afr[mi][1]), "r"(afr[mi][2]), "r"(afr[mi][3]),
                          "r"(bfr[ni][0]), "r"(bfr[ni][1]));
        }
        __syncthreads();
        if (c + 2 < NC) ISSUE(s, c + 2);
    }
#undef ISSUE

    // epilogue: thread (lane) holds (m = g, n = 2t) pairs
    #pragma unroll
    for (int mi = 0; mi < 4; mi++) {
        int mrow0 = bm + wm * 64 + mi * 16 + (lane >> 2);
        #pragma unroll
        for (int hh = 0; hh < 2; hh++) {
            int m = mrow0 + hh * 8;
            size_t rb = (size_t)m * Nn + bn + wn * 32 + 2 * (lane & 3);
            #pragma unroll
            for (int ni = 0; ni < 4; ni++) {
                size_t off = rb + ni * 8;
                float2 val = make_float2(acc[mi][ni][hh * 2 + 0], acc[mi][ni][hh * 2 + 1]);
                if (R) {
                    float2 rv = *(const float2*)(R + off);
                    val.x += rv.x; val.y += rv.y;
                }
                *(float2*)(C + off) = val;
            }
        }
    }
}

// ---------------- RoPE (applies to q and k in-place, fp32) ----------------
__global__ __launch_bounds__(256) void rope_kernel(
    float* __restrict__ q, float* __restrict__ k,
    const float* __restrict__ cs, const float* __restrict__ sn)
{
    int p = blockIdx.x * blockDim.x + threadIdx.x;
    const int npairs = MTOT * (DIMV / 2);
    if (p >= npairs) return;
    int row = p / (DIMV / 2);
    int rem = p - row * (DIMV / 2);
    int i = rem & 63;
    int s = row & (SEQ - 1);
    float c = cs[s * 64 + i];
    float si = sn[s * 64 + i];
    size_t base = (size_t)row * DIMV + 2 * rem;
    float a = q[base], b = q[base + 1];
    q[base]     = a * c - b * si;
    q[base + 1] = a * si + b * c;
    a = k[base]; b = k[base + 1];
    k[base]     = a * c - b * si;
    k[base + 1] = a * si + b * c;
}

// ---------------- Flash attention (causal), 64x64 tiles, fp32, half out ----------------
__global__ __launch_bounds__(256) void attn_kernel(
    const float* __restrict__ Q, const float* __restrict__ K,
    const float* __restrict__ V, __half* __restrict__ O)
{
    extern __shared__ float sm[];
    float* Qt = sm;
    float* Kt = Qt + HD * 64;
    float* Vs = Kt + HD * 64;
    float* Ps = Vs + 64 * 132;
    float* mrow = Ps + 64 * 65;
    float* lrow = mrow + 64;
    float* arow = lrow + 64;

    const int qt = blockIdx.x, bh = blockIdx.y;
    const int b = bh >> 4, h = bh & 15;
    const int tid = threadIdx.x;
    const int tx = tid & 15, ty = tid >> 4;
    const int q0 = qt * 64;
    const size_t headoff = (size_t)h * HD;
    const float scale = 0.08838834764831845f;

    {
        int r = tid & 63, c0 = (tid >> 6) * 32;
        const float* src = Q + (size_t)(b * SEQ + q0 + r) * DIMV + headoff + c0;
        #pragma unroll
        for (int i = 0; i < 8; i++) {
            float4 v = *(const float4*)(src + 4 * i);
            int d = c0 + 4 * i;
            Qt[(d + 0) * 64 + r] = v.x;
            Qt[(d + 1) * 64 + r] = v.y;
            Qt[(d + 2) * 64 + r] = v.z;
            Qt[(d + 3) * 64 + r] = v.w;
        }
    }
    if (tid < 64) { mrow[tid] = -INFINITY; lrow[tid] = 0.f; }

    float o[4][8];
    #pragma unroll
    for (int i = 0; i < 4; i++)
        #pragma unroll
        for (int j = 0; j < 8; j++) o[i][j] = 0.f;

    for (int kt = 0; kt <= qt; kt++) {
        int k0 = kt * 64;
        __syncthreads();
        {
            int r = tid & 63, c0 = (tid >> 6) * 32;
            const float* ksrc = K + (size_t)(b * SEQ + k0 + r) * DIMV + headoff + c0;
            const float* vsrc = V + (size_t)(b * SEQ + k0 + r) * DIMV + headoff + c0;
            #pragma unroll
            for (int i = 0; i < 8; i++) {
                float4 kv = *(const float4*)(ksrc + 4 * i);
                int d = c0 + 4 * i;
                Kt[(d + 0) * 64 + r] = kv.x;
                Kt[(d + 1) * 64 + r] = kv.y;
                Kt[(d + 2) * 64 + r] = kv.z;
                Kt[(d + 3) * 64 + r] = kv.w;
                float4 vv = *(const float4*)(vsrc + 4 * i);
                *(float4*)&Vs[r * 132 + c0 + 4 * i] = vv;
            }
        }
        __syncthreads();

        float sacc[4][4];
        #pragma unroll
        for (int i = 0; i < 4; i++)
            #pragma unroll
            for (int j = 0; j < 4; j++) sacc[i][j] = 0.f;
        for (int d = 0; d < HD; d++) {
            float qf[4], kf[4];
            *(float4*)qf = *(const float4*)&Qt[d * 64 + ty * 4];
            *(float4*)kf = *(const float4*)&Kt[d * 64 + tx * 4];
            #pragma unroll
            for (int i = 0; i < 4; i++)
                #pragma unroll
                for (int j = 0; j < 4; j++)
                    sacc[i][j] = fmaf(qf[i], kf[j], sacc[i][j]);
        }
        #pragma unroll
        for (int i = 0; i < 4; i++)
            #pragma unroll
            for (int j = 0; j < 4; j++)
                Ps[(ty * 4 + i) * 65 + tx * 4 + j] = sacc[i][j] * scale;
        __syncthreads();

        if (tid < 64) {
            int r = tid;
            int kvalid = (kt == qt) ? (r + 1) : 64;
            float mprev = mrow[r];
            float mx = mprev;
            float* prow = Ps + r * 65;
            for (int j = 0; j < kvalid; j++) mx = fmaxf(mx, prow[j]);
            float sum = 0.f;
            for (int j = 0; j < 64; j++) {
                float pv = (j < kvalid) ? __expf(prow[j] - mx) : 0.f;
                prow[j] = pv;
                sum += pv;
            }
            float alpha = __expf(mprev - mx);
            lrow[r] = lrow[r] * alpha + sum;
            mrow[r] = mx;
            arow[r] = alpha;
        }
        __syncthreads();

        float al[4];
        #pragma unroll
        for (int i = 0; i < 4; i++) al[i] = arow[ty * 4 + i];
        #pragma unroll
        for (int i = 0; i < 4; i++)
            #pragma unroll
            for (int j = 0; j < 8; j++) o[i][j] *= al[i];
        for (int jj = 0; jj < 64; jj++) {
            float vf[8];
            *(float4*)(vf)     = *(const float4*)&Vs[jj * 132 + tx * 8];
            *(float4*)(vf + 4) = *(const float4*)&Vs[jj * 132 + tx * 8 + 4];
            float pf[4];
            #pragma unroll
            for (int i = 0; i < 4; i++) pf[i] = Ps[(ty * 4 + i) * 65 + jj];
            #pragma unroll
            for (int i = 0; i < 4; i++)
                #pragma unroll
                for (int j = 0; j < 8; j++)
                    o[i][j] = fmaf(pf[i], vf[j], o[i][j]);
        }
    }

    float linv[4];
    #pragma unroll
    for (int i = 0; i < 4; i++) linv[i] = 1.f / lrow[ty * 4 + i];
    #pragma unroll
    for (int i = 0; i < 4; i++) {
        __half* dst = O + (size_t)(b * SEQ + q0 + ty * 4 + i) * DIMV + headoff + tx * 8;
        __half2 p0 = __floats2half2_rn(o[i][0] * linv[i], o[i][1] * linv[i]);
        __half2 p1 = __floats2half2_rn(o[i][2] * linv[i], o[i][3] * linv[i]);
        __half2 p2 = __floats2half2_rn(o[i][4] * linv[i], o[i][5] * linv[i]);
        __half2 p3 = __floats2half2_rn(o[i][6] * linv[i], o[i][7] * linv[i]);
        *(__half2*)(dst)     = p0;
        *(__half2*)(dst + 2) = p1;
        *(__half2*)(dst + 4) = p2;
        *(__half2*)(dst + 6) = p3;
    }
}

// ---------------- silu(h1) * h3 -> half ----------------
__global__ __launch_bounds__(256) void silu_mul_kernel(
    const float* __restrict__ h1, const float* __restrict__ h3,
    __half* __restrict__ out, int n)
{
    int i = (blockIdx.x * blockDim.x + threadIdx.x) * 2;
    if (i < n) {
        float2 a = *(const float2*)(h1 + i);
        float2 b = *(const float2*)(h3 + i);
        float g0 = a.x / (1.f + __expf(-a.x)) * b.x;
        float g1 = a.y / (1.f + __expf(-a.y)) * b.y;
        *(__half2*)(out + i) = __floats2half2_rn(g0, g1);
    }
}

// ---------------- launch ----------------
extern "C" void kernel_launch(void* const* d_in, const int* in_sizes, int n_in,
                              void* d_out, int out_size)
{
    const float* x    = (const float*)d_in[0];
    const float* fcos = (const float*)d_in[1];
    const float* fsin = (const float*)d_in[2];
    const float* wq   = (const float*)d_in[4];
    const float* wk   = (const float*)d_in[5];
    const float* wv   = (const float*)d_in[6];
    const float* wo   = (const float*)d_in[7];
    const float* w1   = (const float*)d_in[8];
    const float* w2   = (const float*)d_in[9];
    const float* w3   = (const float*)d_in[10];
    const float* anw  = (const float*)d_in[11];
    const float* fnw  = (const float*)d_in[12];
    float* out = (float*)d_out;

    __half *xnh, *ath, *g1h;
    float *q, *k, *v, *h, *h1, *h3;
    __half *wqT, *wkT, *wvT, *woT, *w1T, *w3T, *w2T;
    cudaGetSymbolAddress((void**)&xnh, g_xnh);
    cudaGetSymbolAddress((void**)&q,  g_q);
    cudaGetSymbolAddress((void**)&k,  g_k);
    cudaGetSymbolAddress((void**)&v,  g_v);
    cudaGetSymbolAddress((void**)&ath, g_ath);
    cudaGetSymbolAddress((void**)&h,  g_h);
    cudaGetSymbolAddress((void**)&h1, g_h1);
    cudaGetSymbolAddress((void**)&h3, g_h3);
    cudaGetSymbolAddress((void**)&g1h, g_g1h);
    cudaGetSymbolAddress((void**)&wqT, g_wqT);
    cudaGetSymbolAddress((void**)&wkT, g_wkT);
    cudaGetSymbolAddress((void**)&wvT, g_wvT);
    cudaGetSymbolAddress((void**)&woT, g_woT);
    cudaGetSymbolAddress((void**)&w1T, g_w1T);
    cudaGetSymbolAddress((void**)&w3T, g_w3T);
    cudaGetSymbolAddress((void**)&w2T, g_w2T);

    const int attn_smem = (HD * 64 * 2 + 64 * 132 + 64 * 65 + 192) * (int)sizeof(float);
    cudaFuncSetAttribute(attn_kernel, cudaFuncAttributeMaxDynamicSharedMemorySize, attn_smem);
    const int gemm_smem = 4 * TILE_H * (int)sizeof(__half);   // 40960
    cudaFuncSetAttribute(gemm_hmma, cudaFuncAttributeMaxDynamicSharedMemorySize, gemm_smem);

    // 0. transpose + convert weights to half [N][K]
    {
        dim3 blk(32, 8);
        transpose_h_kernel<<<dim3(DIMV/32, DIMV/32), blk>>>(wq, wqT, DIMV, DIMV);
        transpose_h_kernel<<<dim3(DIMV/32, DIMV/32), blk>>>(wk, wkT, DIMV, DIMV);
        transpose_h_kernel<<<dim3(DIMV/32, DIMV/32), blk>>>(wv, wvT, DIMV, DIMV);
        transpose_h_kernel<<<dim3(DIMV/32, DIMV/32), blk>>>(wo, woT, DIMV, DIMV);
        transpose_h_kernel<<<dim3(HIDDEN/32, DIMV/32), blk>>>(w1, w1T, DIMV, HIDDEN);
        transpose_h_kernel<<<dim3(HIDDEN/32, DIMV/32), blk>>>(w3, w3T, DIMV, HIDDEN);
        transpose_h_kernel<<<dim3(DIMV/32, HIDDEN/32), blk>>>(w2, w2T, HIDDEN, DIMV);
    }

    // 1. xn = rmsnorm(x, attn_norm_w)  (half)
    rmsnorm_kernel<<<MTOT, 256>>>(x, anw, xnh);

    // 2-4. q/k/v = xn @ wq/wk/wv  (HMMA fp16)
    dim3 gqkv(DIMV / GBN, MTOT / GBM);
    gemm_hmma<<<gqkv, 256, gemm_smem>>>(xnh, wqT, nullptr, q, MTOT, DIMV, DIMV);
    gemm_hmma<<<gqkv, 256, gemm_smem>>>(xnh, wkT, nullptr, k, MTOT, DIMV, DIMV);
    gemm_hmma<<<gqkv, 256, gemm_smem>>>(xnh, wvT, nullptr, v, MTOT, DIMV, DIMV);

    // 5. RoPE on q,k
    {
        int npairs = MTOT * (DIMV / 2);
        rope_kernel<<<(npairs + 255) / 256, 256>>>(q, k, fcos, fsin);
    }

    // 6. causal attention (fp32, writes half)
    attn_kernel<<<dim3(SEQ / 64, BATCH * NHEADS), 256, attn_smem>>>(q, k, v, ath);

    // 7. h = x + at @ wo
    gemm_hmma<<<gqkv, 256, gemm_smem>>>(ath, woT, x, h, MTOT, DIMV, DIMV);

    // 8. hn = rmsnorm(h, ffn_norm_w)  (half, reuse buffer)
    rmsnorm_kernel<<<MTOT, 256>>>(h, fnw, xnh);

    // 9-10. h1 = hn @ w1 ; h3 = hn @ w3
    dim3 gffn(HIDDEN / GBN, MTOT / GBM);
    gemm_hmma<<<gffn, 256, gemm_smem>>>(xnh, w1T, nullptr, h1, MTOT, HIDDEN, DIMV);
    gemm_hmma<<<gffn, 256, gemm_smem>>>(xnh, w3T, nullptr, h3, MTOT, HIDDEN, DIMV);

    // 11. g1 = silu(h1) * h3  (half)
    {
        int n = MTOT * HIDDEN;
        silu_mul_kernel<<<(n / 2 + 255) / 256, 256>>>(h1, h3, g1h, n);
    }

    // 12. out = h + g1 @ w2
    gemm_hmma<<<gqkv, 256, gemm_smem>>>(g1h, w2T, h, out, MTOT, DIMV, HIDDEN);
}

// round 6
// speedup vs baseline: 6.0891x; 1.6468x over previous
#include <cuda_runtime.h>
#include <cuda_fp16.h>
#include <math.h>
#include <stdint.h>

#define DIMV    2048
#define NHEADS  16
#define HD      128
#define HIDDEN  8192
#define BATCH   2
#define SEQ     2048
#define MTOT    (BATCH*SEQ)
#define EPSV    1e-6f

// ---------------- scratch ----------------
__device__ __half g_xnh[MTOT*DIMV];
__device__ __half g_qh [MTOT*DIMV];
__device__ __half g_kh [MTOT*DIMV];
__device__ __half g_vh [MTOT*DIMV];
__device__ __half g_ath[MTOT*DIMV];
__device__ float  g_h  [MTOT*DIMV];
__device__ float  g_h1 [MTOT*HIDDEN];
__device__ float  g_h3 [MTOT*HIDDEN];
__device__ __half g_g1h[MTOT*HIDDEN];
__device__ __half g_wqT[DIMV*DIMV];
__device__ __half g_wkT[DIMV*DIMV];
__device__ __half g_wvT[DIMV*DIMV];
__device__ __half g_woT[DIMV*DIMV];
__device__ __half g_w1T[HIDDEN*DIMV];
__device__ __half g_w3T[HIDDEN*DIMV];
__device__ __half g_w2T[DIMV*HIDDEN];

__device__ __forceinline__ uint32_t smem_u32(const void* p) {
    uint32_t a;
    asm("{ .reg .u64 t; cvta.to.shared.u64 t, %1; cvt.u32.u64 %0, t; }" : "=r"(a) : "l"(p));
    return a;
}
__device__ __forceinline__ uint32_t h2_to_u32(__half2 h) {
    union { __half2 h2; uint32_t u; } cvt;
    cvt.h2 = h;
    return cvt.u;
}
__device__ __forceinline__ void mma16816(float* c, const uint32_t* a, const uint32_t* b) {
    asm volatile("mma.sync.aligned.m16n8k16.row.col.f32.f16.f16.f32 "
        "{%0,%1,%2,%3}, {%4,%5,%6,%7}, {%8,%9}, {%0,%1,%2,%3};"
        : "+f"(c[0]), "+f"(c[1]), "+f"(c[2]), "+f"(c[3])
        : "r"(a[0]), "r"(a[1]), "r"(a[2]), "r"(a[3]), "r"(b[0]), "r"(b[1]));
}
__device__ __forceinline__ void ldsm_x4(uint32_t* r, uint32_t addr) {
    asm volatile("ldmatrix.sync.aligned.m8n8.x4.shared.b16 {%0,%1,%2,%3}, [%4];"
        : "=r"(r[0]), "=r"(r[1]), "=r"(r[2]), "=r"(r[3]) : "r"(addr));
}
__device__ __forceinline__ void ldsm_x4_t(uint32_t* r, uint32_t addr) {
    asm volatile("ldmatrix.sync.aligned.m8n8.x4.trans.shared.b16 {%0,%1,%2,%3}, [%4];"
        : "=r"(r[0]), "=r"(r[1]), "=r"(r[2]), "=r"(r[3]) : "r"(addr));
}

// ---------------- RMSNorm (fp32 in, half out) ----------------
__global__ __launch_bounds__(256) void rmsnorm_kernel(
    const float* __restrict__ x, const float* __restrict__ w, __half* __restrict__ y)
{
    int row = blockIdx.x;
    const float* xr = x + (size_t)row * DIMV;
    float ss = 0.f;
    for (int i = threadIdx.x * 4; i < DIMV; i += blockDim.x * 4) {
        float4 v = *(const float4*)(xr + i);
        ss += v.x*v.x + v.y*v.y + v.z*v.z + v.w*v.w;
    }
    __shared__ float red[8];
    for (int o = 16; o > 0; o >>= 1) ss += __shfl_down_sync(0xffffffffu, ss, o);
    int warp = threadIdx.x >> 5, lane = threadIdx.x & 31;
    if (lane == 0) red[warp] = ss;
    __syncthreads();
    if (warp == 0) {
        float t = (lane < 8) ? red[lane] : 0.f;
        for (int o = 4; o > 0; o >>= 1) t += __shfl_down_sync(0xffffffffu, t, o);
        if (lane == 0) red[0] = t;
    }
    __syncthreads();
    float r = rsqrtf(red[0] / (float)DIMV + EPSV);
    __half* yr = y + (size_t)row * DIMV;
    for (int i = threadIdx.x * 4; i < DIMV; i += blockDim.x * 4) {
        float4 v = *(const float4*)(xr + i);
        float4 ww = *(const float4*)(w + i);
        *(__half2*)(yr + i)     = __floats2half2_rn(v.x * r * ww.x, v.y * r * ww.y);
        *(__half2*)(yr + i + 2) = __floats2half2_rn(v.z * r * ww.z, v.w * r * ww.w);
    }
}

// ---------------- transpose + fp32->half ----------------
__global__ __launch_bounds__(256) void transpose_h_kernel(
    const float* __restrict__ src, __half* __restrict__ dst, int R, int C)
{
    __shared__ float t[32][33];
    int bx = blockIdx.x * 32, by = blockIdx.y * 32;
    #pragma unroll
    for (int i = threadIdx.y; i < 32; i += 8)
        t[i][threadIdx.x] = src[(size_t)(by + i) * C + bx + threadIdx.x];
    __syncthreads();
    #pragma unroll
    for (int i = threadIdx.y; i < 32; i += 8)
        dst[(size_t)(bx + i) * R + by + threadIdx.x] = __float2half(t[threadIdx.x][i]);
}

// ---------------- HMMA fp16 GEMM (templated output) ----------------
#define GBM 128
#define GBN 128
#define GBK 32
#define APAD 40
#define TILE_H (128*APAD)

__device__ __forceinline__ void store_pair(float* C, size_t off, float a, float b) {
    *(float2*)(C + off) = make_float2(a, b);
}
__device__ __forceinline__ void store_pair(__half* C, size_t off, float a, float b) {
    *(__half2*)(C + off) = __floats2half2_rn(a, b);
}

template <typename OT>
__global__ __launch_bounds__(256) void gemm_hmma(
    const __half* __restrict__ A, const __half* __restrict__ Bt,
    const float* __restrict__ R, OT* __restrict__ C,
    int Mn, int Nn, int Kn)
{
    extern __shared__ __half hs[];
    __half* As = hs;
    __half* Bs = hs + 2 * TILE_H;
    const int tid = threadIdx.x;
    const int lane = tid & 31, wid = tid >> 5;
    const int wm = wid >> 2, wn = wid & 3;
    const int bm = blockIdx.y * GBM, bn = blockIdx.x * GBN;

    float acc[4][4][4];
    #pragma unroll
    for (int i = 0; i < 4; i++)
        #pragma unroll
        for (int j = 0; j < 4; j++)
            #pragma unroll
            for (int q = 0; q < 4; q++) acc[i][j][q] = 0.f;

    const __half* Ag = A + (size_t)bm * Kn;
    const __half* Bg = Bt + (size_t)bn * Kn;
    const int r0 = tid >> 2, c0 = (tid & 3) * 8;
    const int r1 = (tid + 256) >> 2;
    const uint32_t sA0 = smem_u32(As), sB0 = smem_u32(Bs);
    const int NC = Kn / GBK;

#define ISSUE(stage, c)                                                          \
    {                                                                            \
        int kb = (c) * GBK;                                                      \
        uint32_t sA = sA0 + (stage) * TILE_H * 2;                                \
        uint32_t sB = sB0 + (stage) * TILE_H * 2;                                \
        asm volatile("cp.async.cg.shared.global [%0], [%1], 16;"                 \
                     :: "r"(sA + (r0 * APAD + c0) * 2), "l"(Ag + (size_t)r0 * Kn + kb + c0)); \
        asm volatile("cp.async.cg.shared.global [%0], [%1], 16;"                 \
                     :: "r"(sB + (r0 * APAD + c0) * 2), "l"(Bg + (size_t)r0 * Kn + kb + c0)); \
        asm volatile("cp.async.cg.shared.global [%0], [%1], 16;"                 \
                     :: "r"(sA + (r1 * APAD + c0) * 2), "l"(Ag + (size_t)r1 * Kn + kb + c0)); \
        asm volatile("cp.async.cg.shared.global [%0], [%1], 16;"                 \
                     :: "r"(sB + (r1 * APAD + c0) * 2), "l"(Bg + (size_t)r1 * Kn + kb + c0)); \
        asm volatile("cp.async.commit_group;" ::: "memory");                     \
    }

    ISSUE(0, 0);
    if (NC > 1) ISSUE(1, 1);

    for (int c = 0; c < NC; c++) {
        const int s = c & 1;
        if (c + 1 < NC) asm volatile("cp.async.wait_group 1;" ::: "memory");
        else            asm volatile("cp.async.wait_group 0;" ::: "memory");
        __syncthreads();
        const uint32_t aBase = sA0 + s * TILE_H * 2;
        const uint32_t bBase = sB0 + s * TILE_H * 2;
        #pragma unroll
        for (int kk = 0; kk < 2; kk++) {
            uint32_t afr[4][4], bfr[4][2];
            #pragma unroll
            for (int mi = 0; mi < 4; mi++) {
                int row = wm * 64 + mi * 16 + (lane & 15);
                int col = kk * 16 + (lane >> 4) * 8;
                ldsm_x4(afr[mi], aBase + (row * APAD + col) * 2);
            }
            #pragma unroll
            for (int ni = 0; ni < 4; ni++) {
                int row = wn * 32 + ni * 8 + (lane & 7);
                int col = kk * 16 + ((lane >> 3) & 1) * 8;
                asm volatile("ldmatrix.sync.aligned.m8n8.x2.shared.b16 {%0,%1}, [%2];"
                    : "=r"(bfr[ni][0]), "=r"(bfr[ni][1])
                    : "r"(bBase + (row * APAD + col) * 2));
            }
            #pragma unroll
            for (int mi = 0; mi < 4; mi++)
                #pragma unroll
                for (int ni = 0; ni < 4; ni++)
                    mma16816(acc[mi][ni], afr[mi], bfr[ni]);
        }
        __syncthreads();
        if (c + 2 < NC) ISSUE(s, c + 2);
    }
#undef ISSUE

    #pragma unroll
    for (int mi = 0; mi < 4; mi++) {
        int mrow0 = bm + wm * 64 + mi * 16 + (lane >> 2);
        #pragma unroll
        for (int hh = 0; hh < 2; hh++) {
            int m = mrow0 + hh * 8;
            size_t rb = (size_t)m * Nn + bn + wn * 32 + 2 * (lane & 3);
            #pragma unroll
            for (int ni = 0; ni < 4; ni++) {
                size_t off = rb + ni * 8;
                float va = acc[mi][ni][hh * 2 + 0], vb = acc[mi][ni][hh * 2 + 1];
                if (R) {
                    float2 rv = *(const float2*)(R + off);
                    va += rv.x; vb += rv.y;
                }
                store_pair(C, off, va, vb);
            }
        }
    }
}

// ---------------- RoPE on half ----------------
__global__ __launch_bounds__(256) void rope_h_kernel(
    __half* __restrict__ q, __half* __restrict__ k,
    const float* __restrict__ cs, const float* __restrict__ sn)
{
    int p = blockIdx.x * blockDim.x + threadIdx.x;
    const int npairs = MTOT * (DIMV / 2);
    if (p >= npairs) return;
    int row = p / (DIMV / 2);
    int rem = p - row * (DIMV / 2);
    int i = rem & 63;
    int s = row & (SEQ - 1);
    float c = cs[s * 64 + i];
    float si = sn[s * 64 + i];
    size_t base = (size_t)row * DIMV + 2 * rem;
    __half2* qp = (__half2*)(q + base);
    float2 v = __half22float2(*qp);
    *qp = __floats2half2_rn(v.x * c - v.y * si, v.x * si + v.y * c);
    __half2* kp = (__half2*)(k + base);
    v = __half22float2(*kp);
    *kp = __floats2half2_rn(v.x * c - v.y * si, v.x * si + v.y * c);
}

// ---------------- Flash attention, fp16 mma, causal ----------------
#define BQ  128
#define BKV 64
#define KVS 136   // halves per smem row (272B, conflict-free ldmatrix)

__global__ __launch_bounds__(256) void attn_mma(
    const __half* __restrict__ Qh, const __half* __restrict__ Kh,
    const __half* __restrict__ Vh, __half* __restrict__ O)
{
    extern __shared__ __half kvsm[];
    __half* Ks = kvsm;                     // [2][BKV][KVS]
    __half* Vs = kvsm + 2 * BKV * KVS;     // [2][BKV][KVS]
    const int tid = threadIdx.x, lane = tid & 31, w = tid >> 5;
    const int qt = blockIdx.x, bh = blockIdx.y;
    const int b = bh >> 4, h = bh & 15;
    const int q0 = qt * BQ;
    const int r = lane >> 2, cq = (lane & 3) * 2;
    const float scale = 0.08838834764831845f;

    // Q fragments in registers (8 k-steps x 4 regs)
    uint32_t qf[8][4];
    {
        const __half* Qg  = Qh + (size_t)(b * SEQ + q0 + w * 16 + r) * DIMV + h * HD;
        const __half* Qg8 = Qg + 8 * (size_t)DIMV;
        #pragma unroll
        for (int kk = 0; kk < 8; kk++) {
            qf[kk][0] = *(const uint32_t*)(Qg  + kk * 16 + cq);
            qf[kk][1] = *(const uint32_t*)(Qg8 + kk * 16 + cq);
            qf[kk][2] = *(const uint32_t*)(Qg  + kk * 16 + 8 + cq);
            qf[kk][3] = *(const uint32_t*)(Qg8 + kk * 16 + 8 + cq);
        }
    }

    float oacc[16][4];
    #pragma unroll
    for (int j = 0; j < 16; j++)
        #pragma unroll
        for (int q = 0; q < 4; q++) oacc[j][q] = 0.f;
    float m0 = -1e30f, m1 = -1e30f, l0 = 0.f, l1 = 0.f;

    const uint32_t sKs = smem_u32(Ks), sVs = smem_u32(Vs);
    const __half* Kg = Kh + (size_t)(b * SEQ) * DIMV + h * HD;
    const __half* Vg = Vh + (size_t)(b * SEQ) * DIMV + h * HD;
    const int nkt = qt * 2 + 2;

#define KV_ISSUE(stage, kt)                                                        \
    {                                                                              \
        _Pragma("unroll")                                                          \
        for (int ii = 0; ii < 4; ii++) {                                           \
            int idx = tid + ii * 256;                                              \
            int rr = idx >> 4, cc = (idx & 15) * 8;                                \
            uint32_t doff = (uint32_t)(((stage) * BKV + rr) * KVS + cc) * 2;       \
            asm volatile("cp.async.cg.shared.global [%0], [%1], 16;"               \
                :: "r"(sKs + doff), "l"(Kg + (size_t)((kt) * BKV + rr) * DIMV + cc)); \
            asm volatile("cp.async.cg.shared.global [%0], [%1], 16;"               \
                :: "r"(sVs + doff), "l"(Vg + (size_t)((kt) * BKV + rr) * DIMV + cc)); \
        }                                                                          \
        asm volatile("cp.async.commit_group;" ::: "memory");                       \
    }

    KV_ISSUE(0, 0);
    if (nkt > 1) KV_ISSUE(1, 1);

    for (int kt = 0; kt < nkt; kt++) {
        const int s = kt & 1;
        if (kt + 1 < nkt) asm volatile("cp.async.wait_group 1;" ::: "memory");
        else              asm volatile("cp.async.wait_group 0;" ::: "memory");
        __syncthreads();
        const uint32_t kb = sKs + (uint32_t)(s * BKV * KVS) * 2;
        const uint32_t vb = sVs + (uint32_t)(s * BKV * KVS) * 2;

        // ---- S = Q K^T (m16 x n64) ----
        float sa[8][4];
        #pragma unroll
        for (int j = 0; j < 8; j++)
            #pragma unroll
            for (int q = 0; q < 4; q++) sa[j][q] = 0.f;
        #pragma unroll
        for (int kk = 0; kk < 8; kk++) {
            uint32_t kf[8][2];
            #pragma unroll
            for (int jp = 0; jp < 4; jp++) {
                uint32_t t4[4];
                int nt = jp * 2 + (lane >> 4);
                uint32_t addr = kb + (uint32_t)((nt * 8 + (lane & 7)) * KVS
                                + kk * 16 + ((lane >> 3) & 1) * 8) * 2;
                ldsm_x4(t4, addr);
                kf[jp*2][0] = t4[0]; kf[jp*2][1] = t4[1];
                kf[jp*2+1][0] = t4[2]; kf[jp*2+1][1] = t4[3];
            }
            #pragma unroll
            for (int j = 0; j < 8; j++)
                mma16816(sa[j], qf[kk], kf[j]);
        }

        // ---- scale + causal mask + online softmax ----
        const int row0 = q0 + w * 16 + r, row1 = row0 + 8;
        const bool need_mask = (kt * BKV + BKV - 1) > row0 || (kt * BKV + BKV - 1) > row1;
        float mx0 = -1e30f, mx1 = -1e30f;
        #pragma unroll
        for (int j = 0; j < 8; j++) {
            int col = kt * BKV + j * 8 + cq;
            sa[j][0] *= scale; sa[j][1] *= scale;
            sa[j][2] *= scale; sa[j][3] *= scale;
            if (need_mask) {
                if (col     > row0) sa[j][0] = -1e30f;
                if (col + 1 > row0) sa[j][1] = -1e30f;
                if (col     > row1) sa[j][2] = -1e30f;
                if (col + 1 > row1) sa[j][3] = -1e30f;
            }
            mx0 = fmaxf(mx0, fmaxf(sa[j][0], sa[j][1]));
            mx1 = fmaxf(mx1, fmaxf(sa[j][2], sa[j][3]));
        }
        mx0 = fmaxf(mx0, __shfl_xor_sync(0xffffffffu, mx0, 1));
        mx0 = fmaxf(mx0, __shfl_xor_sync(0xffffffffu, mx0, 2));
        mx1 = fmaxf(mx1, __shfl_xor_sync(0xffffffffu, mx1, 1));
        mx1 = fmaxf(mx1, __shfl_xor_sync(0xffffffffu, mx1, 2));
        float mn0 = fmaxf(m0, mx0), mn1 = fmaxf(m1, mx1);
        float a0 = __expf(m0 - mn0), a1 = __expf(m1 - mn1);
        float s0 = 0.f, s1 = 0.f;
        uint32_t ph[8][2];
        #pragma unroll
        for (int j = 0; j < 8; j++) {
            float p00 = __expf(sa[j][0] - mn0);
            float p01 = __expf(sa[j][1] - mn0);
            float p10 = __expf(sa[j][2] - mn1);
            float p11 = __expf(sa[j][3] - mn1);
            s0 += p00 + p01; s1 += p10 + p11;
            ph[j][0] = h2_to_u32(__floats2half2_rn(p00, p01));
            ph[j][1] = h2_to_u32(__floats2half2_rn(p10, p11));
        }
        s0 += __shfl_xor_sync(0xffffffffu, s0, 1);
        s0 += __shfl_xor_sync(0xffffffffu, s0, 2);
        s1 += __shfl_xor_sync(0xffffffffu, s1, 1);
        s1 += __shfl_xor_sync(0xffffffffu, s1, 2);
        l0 = l0 * a0 + s0; l1 = l1 * a1 + s1;
        m0 = mn0; m1 = mn1;
        #pragma unroll
        for (int j = 0; j < 16; j++) {
            oacc[j][0] *= a0; oacc[j][1] *= a0;
            oacc[j][2] *= a1; oacc[j][3] *= a1;
        }

        // ---- O += P V ----
        #pragma unroll
        for (int kk2 = 0; kk2 < 4; kk2++) {
            uint32_t pa[4] = { ph[kk2*2][0], ph[kk2*2][1], ph[kk2*2+1][0], ph[kk2*2+1][1] };
            #pragma unroll
            for (int jp = 0; jp < 8; jp++) {
                uint32_t vt[4];
                uint32_t addr = vb + (uint32_t)((kk2 * 16 + (lane & 15)) * KVS
                                + (jp * 2 + (lane >> 4)) * 8) * 2;
                ldsm_x4_t(vt, addr);
                mma16816(oacc[jp*2],     pa, &vt[0]);
                mma16816(oacc[jp*2 + 1], pa, &vt[2]);
            }
        }
        __syncthreads();
        if (kt + 2 < nkt) KV_ISSUE(s, kt + 2);
    }
#undef KV_ISSUE

    float i0 = 1.f / l0, i1 = 1.f / l1;
    __half* Og  = O + (size_t)(b * SEQ + q0 + w * 16 + r) * DIMV + h * HD + cq;
    __half* Og8 = Og + 8 * (size_t)DIMV;
    #pragma unroll
    for (int j = 0; j < 16; j++) {
        *(__half2*)(Og  + j * 8) = __floats2half2_rn(oacc[j][0] * i0, oacc[j][1] * i0);
        *(__half2*)(Og8 + j * 8) = __floats2half2_rn(oacc[j][2] * i1, oacc[j][3] * i1);
    }
}

// ---------------- silu(h1)*h3 -> half ----------------
__global__ __launch_bounds__(256) void silu_mul_kernel(
    const float* __restrict__ h1, const float* __restrict__ h3,
    __half* __restrict__ out, int n)
{
    int i = (blockIdx.x * blockDim.x + threadIdx.x) * 2;
    if (i < n) {
        float2 a = *(const float2*)(h1 + i);
        float2 b = *(const float2*)(h3 + i);
        float g0 = a.x / (1.f + __expf(-a.x)) * b.x;
        float g1 = a.y / (1.f + __expf(-a.y)) * b.y;
        *(__half2*)(out + i) = __floats2half2_rn(g0, g1);
    }
}

// ---------------- launch ----------------
extern "C" void kernel_launch(void* const* d_in, const int* in_sizes, int n_in,
                              void* d_out, int out_size)
{
    const float* x    = (const float*)d_in[0];
    const float* fcos = (const float*)d_in[1];
    const float* fsin = (const float*)d_in[2];
    const float* wq   = (const float*)d_in[4];
    const float* wk   = (const float*)d_in[5];
    const float* wv   = (const float*)d_in[6];
    const float* wo   = (const float*)d_in[7];
    const float* w1   = (const float*)d_in[8];
    const float* w2   = (const float*)d_in[9];
    const float* w3   = (const float*)d_in[10];
    const float* anw  = (const float*)d_in[11];
    const float* fnw  = (const float*)d_in[12];
    float* out = (float*)d_out;

    __half *xnh, *qh, *kh, *vh, *ath, *g1h;
    float *h, *h1, *h3;
    __half *wqT, *wkT, *wvT, *woT, *w1T, *w3T, *w2T;
    cudaGetSymbolAddress((void**)&xnh, g_xnh);
    cudaGetSymbolAddress((void**)&qh,  g_qh);
    cudaGetSymbolAddress((void**)&kh,  g_kh);
    cudaGetSymbolAddress((void**)&vh,  g_vh);
    cudaGetSymbolAddress((void**)&ath, g_ath);
    cudaGetSymbolAddress((void**)&h,   g_h);
    cudaGetSymbolAddress((void**)&h1,  g_h1);
    cudaGetSymbolAddress((void**)&h3,  g_h3);
    cudaGetSymbolAddress((void**)&g1h, g_g1h);
    cudaGetSymbolAddress((void**)&wqT, g_wqT);
    cudaGetSymbolAddress((void**)&wkT, g_wkT);
    cudaGetSymbolAddress((void**)&wvT, g_wvT);
    cudaGetSymbolAddress((void**)&woT, g_woT);
    cudaGetSymbolAddress((void**)&w1T, g_w1T);
    cudaGetSymbolAddress((void**)&w3T, g_w3T);
    cudaGetSymbolAddress((void**)&w2T, g_w2T);

    const int gemm_smem = 4 * TILE_H * (int)sizeof(__half);
    cudaFuncSetAttribute(gemm_hmma<float>,  cudaFuncAttributeMaxDynamicSharedMemorySize, gemm_smem);
    cudaFuncSetAttribute(gemm_hmma<__half>, cudaFuncAttributeMaxDynamicSharedMemorySize, gemm_smem);
    const int attn_smem = 4 * BKV * KVS * (int)sizeof(__half);  // 69632
    cudaFuncSetAttribute(attn_mma, cudaFuncAttributeMaxDynamicSharedMemorySize, attn_smem);

    // 0. weights -> half [N][K]
    {
        dim3 blk(32, 8);
        transpose_h_kernel<<<dim3(DIMV/32, DIMV/32), blk>>>(wq, wqT, DIMV, DIMV);
        transpose_h_kernel<<<dim3(DIMV/32, DIMV/32), blk>>>(wk, wkT, DIMV, DIMV);
        transpose_h_kernel<<<dim3(DIMV/32, DIMV/32), blk>>>(wv, wvT, DIMV, DIMV);
        transpose_h_kernel<<<dim3(DIMV/32, DIMV/32), blk>>>(wo, woT, DIMV, DIMV);
        transpose_h_kernel<<<dim3(HIDDEN/32, DIMV/32), blk>>>(w1, w1T, DIMV, HIDDEN);
        transpose_h_kernel<<<dim3(HIDDEN/32, DIMV/32), blk>>>(w3, w3T, DIMV, HIDDEN);
        transpose_h_kernel<<<dim3(DIMV/32, HIDDEN/32), blk>>>(w2, w2T, HIDDEN, DIMV);
    }

    // 1. xn = rmsnorm(x)
    rmsnorm_kernel<<<MTOT, 256>>>(x, anw, xnh);

    // 2-4. q/k/v (half out)
    dim3 gqkv(DIMV / GBN, MTOT / GBM);
    gemm_hmma<__half><<<gqkv, 256, gemm_smem>>>(xnh, wqT, nullptr, qh, MTOT, DIMV, DIMV);
    gemm_hmma<__half><<<gqkv, 256, gemm_smem>>>(xnh, wkT, nullptr, kh, MTOT, DIMV, DIMV);
    gemm_hmma<__half><<<gqkv, 256, gemm_smem>>>(xnh, wvT, nullptr, vh, MTOT, DIMV, DIMV);

    // 5. RoPE
    {
        int npairs = MTOT * (DIMV / 2);
        rope_h_kernel<<<(npairs + 255) / 256, 256>>>(qh, kh, fcos, fsin);
    }

    // 6. attention (fp16 mma)
    attn_mma<<<dim3(SEQ / BQ, BATCH * NHEADS), 256, attn_smem>>>(qh, kh, vh, ath);

    // 7. h = x + at @ wo
    gemm_hmma<float><<<gqkv, 256, gemm_smem>>>(ath, woT, x, h, MTOT, DIMV, DIMV);

    // 8. hn = rmsnorm(h)
    rmsnorm_kernel<<<MTOT, 256>>>(h, fnw, xnh);

    // 9-10. FFN up
    dim3 gffn(HIDDEN / GBN, MTOT / GBM);
    gemm_hmma<float><<<gffn, 256, gemm_smem>>>(xnh, w1T, nullptr, h1, MTOT, HIDDEN, DIMV);
    gemm_hmma<float><<<gffn, 256, gemm_smem>>>(xnh, w3T, nullptr, h3, MTOT, HIDDEN, DIMV);

    // 11. g1 = silu(h1)*h3
    {
        int n = MTOT * HIDDEN;
        silu_mul_kernel<<<(n / 2 + 255) / 256, 256>>>(h1, h3, g1h, n);
    }

    // 12. out = h + g1 @ w2
    gemm_hmma<float><<<gqkv, 256, gemm_smem>>>(g1h, w2T, h, out, MTOT, DIMV, HIDDEN);
}

// round 7
// speedup vs baseline: 6.3860x; 1.0488x over previous
#include <cuda_runtime.h>
#include <cuda_fp16.h>
#include <math.h>
#include <stdint.h>

#define DIMV    2048
#define NHEADS  16
#define HD      128
#define HIDDEN  8192
#define BATCH   2
#define SEQ     2048
#define MTOT    (BATCH*SEQ)
#define QKVS    (3*DIMV)     // packed qkv row stride
#define EPSV    1e-6f

// ---------------- scratch ----------------
__device__ __half g_xnh [MTOT*DIMV];
__device__ __half g_qkv [MTOT*QKVS];       // packed q|k|v
__device__ __half g_ath [MTOT*DIMV];
__device__ float  g_h   [MTOT*DIMV];
__device__ __half g_g1h [MTOT*HIDDEN];
__device__ __half g_wqkvT[3*DIMV*DIMV];    // concat wqT|wkT|wvT, [6144][2048]
__device__ __half g_woT [DIMV*DIMV];
__device__ __half g_w13i[2*HIDDEN*DIMV];   // interleaved w1/w3 cols, [16384][2048]
__device__ __half g_w2T [DIMV*HIDDEN];

__device__ __forceinline__ uint32_t smem_u32(const void* p) {
    uint32_t a;
    asm("{ .reg .u64 t; cvta.to.shared.u64 t, %1; cvt.u32.u64 %0, t; }" : "=r"(a) : "l"(p));
    return a;
}
__device__ __forceinline__ uint32_t h2_to_u32(__half2 h) {
    union { __half2 h2; uint32_t u; } cvt;
    cvt.h2 = h;
    return cvt.u;
}
__device__ __forceinline__ void mma16816(float* c, const uint32_t* a, const uint32_t* b) {
    asm volatile("mma.sync.aligned.m16n8k16.row.col.f32.f16.f16.f32 "
        "{%0,%1,%2,%3}, {%4,%5,%6,%7}, {%8,%9}, {%0,%1,%2,%3};"
        : "+f"(c[0]), "+f"(c[1]), "+f"(c[2]), "+f"(c[3])
        : "r"(a[0]), "r"(a[1]), "r"(a[2]), "r"(a[3]), "r"(b[0]), "r"(b[1]));
}
__device__ __forceinline__ void ldsm_x4(uint32_t* r, uint32_t addr) {
    asm volatile("ldmatrix.sync.aligned.m8n8.x4.shared.b16 {%0,%1,%2,%3}, [%4];"
        : "=r"(r[0]), "=r"(r[1]), "=r"(r[2]), "=r"(r[3]) : "r"(addr));
}
__device__ __forceinline__ void ldsm_x4_t(uint32_t* r, uint32_t addr) {
    asm volatile("ldmatrix.sync.aligned.m8n8.x4.trans.shared.b16 {%0,%1,%2,%3}, [%4];"
        : "=r"(r[0]), "=r"(r[1]), "=r"(r[2]), "=r"(r[3]) : "r"(addr));
}

// ---------------- RMSNorm (fp32 in, half out) ----------------
__global__ __launch_bounds__(256) void rmsnorm_kernel(
    const float* __restrict__ x, const float* __restrict__ w, __half* __restrict__ y)
{
    int row = blockIdx.x;
    const float* xr = x + (size_t)row * DIMV;
    float ss = 0.f;
    for (int i = threadIdx.x * 4; i < DIMV; i += blockDim.x * 4) {
        float4 v = *(const float4*)(xr + i);
        ss += v.x*v.x + v.y*v.y + v.z*v.z + v.w*v.w;
    }
    __shared__ float red[8];
    for (int o = 16; o > 0; o >>= 1) ss += __shfl_down_sync(0xffffffffu, ss, o);
    int warp = threadIdx.x >> 5, lane = threadIdx.x & 31;
    if (lane == 0) red[warp] = ss;
    __syncthreads();
    if (warp == 0) {
        float t = (lane < 8) ? red[lane] : 0.f;
        for (int o = 4; o > 0; o >>= 1) t += __shfl_down_sync(0xffffffffu, t, o);
        if (lane == 0) red[0] = t;
    }
    __syncthreads();
    float r = rsqrtf(red[0] / (float)DIMV + EPSV);
    __half* yr = y + (size_t)row * DIMV;
    for (int i = threadIdx.x * 4; i < DIMV; i += blockDim.x * 4) {
        float4 v = *(const float4*)(xr + i);
        float4 ww = *(const float4*)(w + i);
        *(__half2*)(yr + i)     = __floats2half2_rn(v.x * r * ww.x, v.y * r * ww.y);
        *(__half2*)(yr + i + 2) = __floats2half2_rn(v.z * r * ww.z, v.w * r * ww.w);
    }
}

// ---------------- transpose + fp32->half (optional column interleave) ----------------
// dst row index = istride*(bx+i) + ioff, row length R
__global__ __launch_bounds__(256) void transpose_h_kernel(
    const float* __restrict__ src, __half* __restrict__ dst, int R, int C,
    int istride, int ioff)
{
    __shared__ float t[32][33];
    int bx = blockIdx.x * 32, by = blockIdx.y * 32;
    #pragma unroll
    for (int i = threadIdx.y; i < 32; i += 8)
        t[i][threadIdx.x] = src[(size_t)(by + i) * C + bx + threadIdx.x];
    __syncthreads();
    #pragma unroll
    for (int i = threadIdx.y; i < 32; i += 8)
        dst[(size_t)(istride * (bx + i) + ioff) * R + by + threadIdx.x]
            = __float2half(t[threadIdx.x][i]);
}

// ---------------- HMMA fp16 GEMM with fused epilogues ----------------
// MODE 0: fp32 out (+R residual)
// MODE 2: half out, RoPE applied for n < 2*DIMV (q,k of packed qkv)
// MODE 3: swiglu: B is col-interleaved w1/w3; out half at col n/2
#define GBM 128
#define GBN 128
#define GBK 32
#define APAD 40
#define TILE_H (128*APAD)

template <int MODE>
__global__ __launch_bounds__(256) void gemm_hmma(
    const __half* __restrict__ A, const __half* __restrict__ Bt,
    const float* __restrict__ R, float* __restrict__ Cf, __half* __restrict__ Ch,
    const float* __restrict__ cs, const float* __restrict__ sn,
    int Mn, int Nn, int Kn)
{
    extern __shared__ __half hs[];
    __half* As = hs;
    __half* Bs = hs + 2 * TILE_H;
    const int tid = threadIdx.x;
    const int lane = tid & 31, wid = tid >> 5;
    const int wm = wid >> 2, wn = wid & 3;
    const int bm = blockIdx.y * GBM, bn = blockIdx.x * GBN;

    float acc[4][4][4];
    #pragma unroll
    for (int i = 0; i < 4; i++)
        #pragma unroll
        for (int j = 0; j < 4; j++)
            #pragma unroll
            for (int q = 0; q < 4; q++) acc[i][j][q] = 0.f;

    const __half* Ag = A + (size_t)bm * Kn;
    const __half* Bg = Bt + (size_t)bn * Kn;
    const int r0 = tid >> 2, c0 = (tid & 3) * 8;
    const int r1 = (tid + 256) >> 2;
    const uint32_t sA0 = smem_u32(As), sB0 = smem_u32(Bs);
    const int NC = Kn / GBK;

#define ISSUE(stage, c)                                                          \
    {                                                                            \
        int kb = (c) * GBK;                                                      \
        uint32_t sA = sA0 + (stage) * TILE_H * 2;                                \
        uint32_t sB = sB0 + (stage) * TILE_H * 2;                                \
        asm volatile("cp.async.cg.shared.global [%0], [%1], 16;"                 \
                     :: "r"(sA + (r0 * APAD + c0) * 2), "l"(Ag + (size_t)r0 * Kn + kb + c0)); \
        asm volatile("cp.async.cg.shared.global [%0], [%1], 16;"                 \
                     :: "r"(sB + (r0 * APAD + c0) * 2), "l"(Bg + (size_t)r0 * Kn + kb + c0)); \
        asm volatile("cp.async.cg.shared.global [%0], [%1], 16;"                 \
                     :: "r"(sA + (r1 * APAD + c0) * 2), "l"(Ag + (size_t)r1 * Kn + kb + c0)); \
        asm volatile("cp.async.cg.shared.global [%0], [%1], 16;"                 \
                     :: "r"(sB + (r1 * APAD + c0) * 2), "l"(Bg + (size_t)r1 * Kn + kb + c0)); \
        asm volatile("cp.async.commit_group;" ::: "memory");                     \
    }

    ISSUE(0, 0);
    if (NC > 1) ISSUE(1, 1);

    for (int c = 0; c < NC; c++) {
        const int s = c & 1;
        if (c + 1 < NC) asm volatile("cp.async.wait_group 1;" ::: "memory");
        else            asm volatile("cp.async.wait_group 0;" ::: "memory");
        __syncthreads();
        const uint32_t aBase = sA0 + s * TILE_H * 2;
        const uint32_t bBase = sB0 + s * TILE_H * 2;
        #pragma unroll
        for (int kk = 0; kk < 2; kk++) {
            uint32_t afr[4][4], bfr[4][2];
            #pragma unroll
            for (int mi = 0; mi < 4; mi++) {
                int row = wm * 64 + mi * 16 + (lane & 15);
                int col = kk * 16 + (lane >> 4) * 8;
                ldsm_x4(afr[mi], aBase + (row * APAD + col) * 2);
            }
            #pragma unroll
            for (int ni = 0; ni < 4; ni++) {
                int row = wn * 32 + ni * 8 + (lane & 7);
                int col = kk * 16 + ((lane >> 3) & 1) * 8;
                asm volatile("ldmatrix.sync.aligned.m8n8.x2.shared.b16 {%0,%1}, [%2];"
                    : "=r"(bfr[ni][0]), "=r"(bfr[ni][1])
                    : "r"(bBase + (row * APAD + col) * 2));
            }
            #pragma unroll
            for (int mi = 0; mi < 4; mi++)
                #pragma unroll
                for (int ni = 0; ni < 4; ni++)
                    mma16816(acc[mi][ni], afr[mi], bfr[ni]);
        }
        __syncthreads();
        if (c + 2 < NC) ISSUE(s, c + 2);
    }
#undef ISSUE

    #pragma unroll
    for (int mi = 0; mi < 4; mi++) {
        int mrow0 = bm + wm * 64 + mi * 16 + (lane >> 2);
        #pragma unroll
        for (int hh = 0; hh < 2; hh++) {
            int m = mrow0 + hh * 8;
            int nb = bn + wn * 32 + 2 * (lane & 3);
            #pragma unroll
            for (int ni = 0; ni < 4; ni++) {
                int n = nb + ni * 8;
                float va = acc[mi][ni][hh * 2 + 0], vb = acc[mi][ni][hh * 2 + 1];
                if (MODE == 0) {
                    size_t off = (size_t)m * Nn + n;
                    if (R) {
                        float2 rv = *(const float2*)(R + off);
                        va += rv.x; vb += rv.y;
                    }
                    *(float2*)(Cf + off) = make_float2(va, vb);
                } else if (MODE == 2) {
                    size_t off = (size_t)m * Nn + n;
                    if (n < 2 * DIMV) {
                        int i2 = (n & (HD - 1)) >> 1;
                        int sidx = m & (SEQ - 1);
                        float cc = cs[sidx * (HD / 2) + i2];
                        float si = sn[sidx * (HD / 2) + i2];
                        float ra = va * cc - vb * si;
                        float rb = va * si + vb * cc;
                        *(__half2*)(Ch + off) = __floats2half2_rn(ra, rb);
                    } else {
                        *(__half2*)(Ch + off) = __floats2half2_rn(va, vb);
                    }
                } else {  // MODE 3: swiglu
                    float g = va / (1.f + __expf(-va)) * vb;
                    Ch[(size_t)m * (Nn >> 1) + (n >> 1)] = __float2half(g);
                }
            }
        }
    }
}

// ---------------- Flash attention, fp16 mma, causal (packed qkv input) ----------------
#define BQ  128
#define BKV 64
#define KVS 136

__global__ __launch_bounds__(256) void attn_mma(
    const __half* __restrict__ QKV, __half* __restrict__ O)
{
    extern __shared__ __half kvsm[];
    __half* Ks = kvsm;
    __half* Vs = kvsm + 2 * BKV * KVS;
    const int tid = threadIdx.x, lane = tid & 31, w = tid >> 5;
    const int qt = blockIdx.x, bh = blockIdx.y;
    const int b = bh >> 4, h = bh & 15;
    const int q0 = qt * BQ;
    const int r = lane >> 2, cq = (lane & 3) * 2;
    const float scale = 0.08838834764831845f;

    uint32_t qf[8][4];
    {
        const __half* Qg  = QKV + (size_t)(b * SEQ + q0 + w * 16 + r) * QKVS + h * HD;
        const __half* Qg8 = Qg + 8 * (size_t)QKVS;
        #pragma unroll
        for (int kk = 0; kk < 8; kk++) {
            qf[kk][0] = *(const uint32_t*)(Qg  + kk * 16 + cq);
            qf[kk][1] = *(const uint32_t*)(Qg8 + kk * 16 + cq);
            qf[kk][2] = *(const uint32_t*)(Qg  + kk * 16 + 8 + cq);
            qf[kk][3] = *(const uint32_t*)(Qg8 + kk * 16 + 8 + cq);
        }
    }

    float oacc[16][4];
    #pragma unroll
    for (int j = 0; j < 16; j++)
        #pragma unroll
        for (int q = 0; q < 4; q++) oacc[j][q] = 0.f;
    float m0 = -1e30f, m1 = -1e30f, l0 = 0.f, l1 = 0.f;

    const uint32_t sKs = smem_u32(Ks), sVs = smem_u32(Vs);
    const __half* Kg = QKV + (size_t)(b * SEQ) * QKVS + DIMV + h * HD;
    const __half* Vg = QKV + (size_t)(b * SEQ) * QKVS + 2 * DIMV + h * HD;
    const int nkt = qt * 2 + 2;

#define KV_ISSUE(stage, kt)                                                        \
    {                                                                              \
        _Pragma("unroll")                                                          \
        for (int ii = 0; ii < 4; ii++) {                                           \
            int idx = tid + ii * 256;                                              \
            int rr = idx >> 4, cc = (idx & 15) * 8;                                \
            uint32_t doff = (uint32_t)(((stage) * BKV + rr) * KVS + cc) * 2;       \
            asm volatile("cp.async.cg.shared.global [%0], [%1], 16;"               \
                :: "r"(sKs + doff), "l"(Kg + (size_t)((kt) * BKV + rr) * QKVS + cc)); \
            asm volatile("cp.async.cg.shared.global [%0], [%1], 16;"               \
                :: "r"(sVs + doff), "l"(Vg + (size_t)((kt) * BKV + rr) * QKVS + cc)); \
        }                                                                          \
        asm volatile("cp.async.commit_group;" ::: "memory");                       \
    }

    KV_ISSUE(0, 0);
    if (nkt > 1) KV_ISSUE(1, 1);

    for (int kt = 0; kt < nkt; kt++) {
        const int s = kt & 1;
        if (kt + 1 < nkt) asm volatile("cp.async.wait_group 1;" ::: "memory");
        else              asm volatile("cp.async.wait_group 0;" ::: "memory");
        __syncthreads();
        const uint32_t kb = sKs + (uint32_t)(s * BKV * KVS) * 2;
        const uint32_t vb = sVs + (uint32_t)(s * BKV * KVS) * 2;

        float sa[8][4];
        #pragma unroll
        for (int j = 0; j < 8; j++)
            #pragma unroll
            for (int q = 0; q < 4; q++) sa[j][q] = 0.f;
        #pragma unroll
        for (int kk = 0; kk < 8; kk++) {
            uint32_t kf[8][2];
            #pragma unroll
            for (int jp = 0; jp < 4; jp++) {
                uint32_t t4[4];
                int nt = jp * 2 + (lane >> 4);
                uint32_t addr = kb + (uint32_t)((nt * 8 + (lane & 7)) * KVS
                                + kk * 16 + ((lane >> 3) & 1) * 8) * 2;
                ldsm_x4(t4, addr);
                kf[jp*2][0] = t4[0]; kf[jp*2][1] = t4[1];
                kf[jp*2+1][0] = t4[2]; kf[jp*2+1][1] = t4[3];
            }
            #pragma unroll
            for (int j = 0; j < 8; j++)
                mma16816(sa[j], qf[kk], kf[j]);
        }

        const int row0 = q0 + w * 16 + r, row1 = row0 + 8;
        const bool need_mask = (kt * BKV + BKV - 1) > row0 || (kt * BKV + BKV - 1) > row1;
        float mx0 = -1e30f, mx1 = -1e30f;
        #pragma unroll
        for (int j = 0; j < 8; j++) {
            int col = kt * BKV + j * 8 + cq;
            sa[j][0] *= scale; sa[j][1] *= scale;
            sa[j][2] *= scale; sa[j][3] *= scale;
            if (need_mask) {
                if (col     > row0) sa[j][0] = -1e30f;
                if (col + 1 > row0) sa[j][1] = -1e30f;
                if (col     > row1) sa[j][2] = -1e30f;
                if (col + 1 > row1) sa[j][3] = -1e30f;
            }
            mx0 = fmaxf(mx0, fmaxf(sa[j][0], sa[j][1]));
            mx1 = fmaxf(mx1, fmaxf(sa[j][2], sa[j][3]));
        }
        mx0 = fmaxf(mx0, __shfl_xor_sync(0xffffffffu, mx0, 1));
        mx0 = fmaxf(mx0, __shfl_xor_sync(0xffffffffu, mx0, 2));
        mx1 = fmaxf(mx1, __shfl_xor_sync(0xffffffffu, mx1, 1));
        mx1 = fmaxf(mx1, __shfl_xor_sync(0xffffffffu, mx1, 2));
        float mn0 = fmaxf(m0, mx0), mn1 = fmaxf(m1, mx1);
        float a0 = __expf(m0 - mn0), a1 = __expf(m1 - mn1);
        float s0 = 0.f, s1 = 0.f;
        uint32_t ph[8][2];
        #pragma unroll
        for (int j = 0; j < 8; j++) {
            float p00 = __expf(sa[j][0] - mn0);
            float p01 = __expf(sa[j][1] - mn0);
            float p10 = __expf(sa[j][2] - mn1);
            float p11 = __expf(sa[j][3] - mn1);
            s0 += p00 + p01; s1 += p10 + p11;
            ph[j][0] = h2_to_u32(__floats2half2_rn(p00, p01));
            ph[j][1] = h2_to_u32(__floats2half2_rn(p10, p11));
        }
        s0 += __shfl_xor_sync(0xffffffffu, s0, 1);
        s0 += __shfl_xor_sync(0xffffffffu, s0, 2);
        s1 += __shfl_xor_sync(0xffffffffu, s1, 1);
        s1 += __shfl_xor_sync(0xffffffffu, s1, 2);
        l0 = l0 * a0 + s0; l1 = l1 * a1 + s1;
        m0 = mn0; m1 = mn1;
        #pragma unroll
        for (int j = 0; j < 16; j++) {
            oacc[j][0] *= a0; oacc[j][1] *= a0;
            oacc[j][2] *= a1; oacc[j][3] *= a1;
        }

        #pragma unroll
        for (int kk2 = 0; kk2 < 4; kk2++) {
            uint32_t pa[4] = { ph[kk2*2][0], ph[kk2*2][1], ph[kk2*2+1][0], ph[kk2*2+1][1] };
            #pragma unroll
            for (int jp = 0; jp < 8; jp++) {
                uint32_t vt[4];
                uint32_t addr = vb + (uint32_t)((kk2 * 16 + (lane & 15)) * KVS
                                + (jp * 2 + (lane >> 4)) * 8) * 2;
                ldsm_x4_t(vt, addr);
                mma16816(oacc[jp*2],     pa, &vt[0]);
                mma16816(oacc[jp*2 + 1], pa, &vt[2]);
            }
        }
        __syncthreads();
        if (kt + 2 < nkt) KV_ISSUE(s, kt + 2);
    }
#undef KV_ISSUE

    float i0 = 1.f / l0, i1 = 1.f / l1;
    __half* Og  = O + (size_t)(b * SEQ + q0 + w * 16 + r) * DIMV + h * HD + cq;
    __half* Og8 = Og + 8 * (size_t)DIMV;
    #pragma unroll
    for (int j = 0; j < 16; j++) {
        *(__half2*)(Og  + j * 8) = __floats2half2_rn(oacc[j][0] * i0, oacc[j][1] * i0);
        *(__half2*)(Og8 + j * 8) = __floats2half2_rn(oacc[j][2] * i1, oacc[j][3] * i1);
    }
}

// ---------------- launch ----------------
extern "C" void kernel_launch(void* const* d_in, const int* in_sizes, int n_in,
                              void* d_out, int out_size)
{
    const float* x    = (const float*)d_in[0];
    const float* fcos = (const float*)d_in[1];
    const float* fsin = (const float*)d_in[2];
    const float* wq   = (const float*)d_in[4];
    const float* wk   = (const float*)d_in[5];
    const float* wv   = (const float*)d_in[6];
    const float* wo   = (const float*)d_in[7];
    const float* w1   = (const float*)d_in[8];
    const float* w2   = (const float*)d_in[9];
    const float* w3   = (const float*)d_in[10];
    const float* anw  = (const float*)d_in[11];
    const float* fnw  = (const float*)d_in[12];
    float* out = (float*)d_out;

    __half *xnh, *qkv, *ath, *g1h;
    float *h;
    __half *wqkvT, *woT, *w13i, *w2T;
    cudaGetSymbolAddress((void**)&xnh,   g_xnh);
    cudaGetSymbolAddress((void**)&qkv,   g_qkv);
    cudaGetSymbolAddress((void**)&ath,   g_ath);
    cudaGetSymbolAddress((void**)&h,     g_h);
    cudaGetSymbolAddress((void**)&g1h,   g_g1h);
    cudaGetSymbolAddress((void**)&wqkvT, g_wqkvT);
    cudaGetSymbolAddress((void**)&woT,   g_woT);
    cudaGetSymbolAddress((void**)&w13i,  g_w13i);
    cudaGetSymbolAddress((void**)&w2T,   g_w2T);

    const int gemm_smem = 4 * TILE_H * (int)sizeof(__half);
    cudaFuncSetAttribute(gemm_hmma<0>, cudaFuncAttributeMaxDynamicSharedMemorySize, gemm_smem);
    cudaFuncSetAttribute(gemm_hmma<2>, cudaFuncAttributeMaxDynamicSharedMemorySize, gemm_smem);
    cudaFuncSetAttribute(gemm_hmma<3>, cudaFuncAttributeMaxDynamicSharedMemorySize, gemm_smem);
    const int attn_smem = 4 * BKV * KVS * (int)sizeof(__half);
    cudaFuncSetAttribute(attn_mma, cudaFuncAttributeMaxDynamicSharedMemorySize, attn_smem);

    // 0. weights -> half, transposed / packed / interleaved
    {
        dim3 blk(32, 8);
        transpose_h_kernel<<<dim3(DIMV/32, DIMV/32), blk>>>(wq, wqkvT,                 DIMV, DIMV, 1, 0);
        transpose_h_kernel<<<dim3(DIMV/32, DIMV/32), blk>>>(wk, wqkvT + DIMV*DIMV,     DIMV, DIMV, 1, 0);
        transpose_h_kernel<<<dim3(DIMV/32, DIMV/32), blk>>>(wv, wqkvT + 2*DIMV*DIMV,   DIMV, DIMV, 1, 0);
        transpose_h_kernel<<<dim3(DIMV/32, DIMV/32), blk>>>(wo, woT, DIMV, DIMV, 1, 0);
        transpose_h_kernel<<<dim3(HIDDEN/32, DIMV/32), blk>>>(w1, w13i, DIMV, HIDDEN, 2, 0);
        transpose_h_kernel<<<dim3(HIDDEN/32, DIMV/32), blk>>>(w3, w13i, DIMV, HIDDEN, 2, 1);
        transpose_h_kernel<<<dim3(DIMV/32, HIDDEN/32), blk>>>(w2, w2T, HIDDEN, DIMV, 1, 0);
    }

    // 1. xn = rmsnorm(x)
    rmsnorm_kernel<<<MTOT, 256>>>(x, anw, xnh);

    // 2. qkv = xn @ [wq|wk|wv], RoPE fused for q,k
    gemm_hmma<2><<<dim3(QKVS / GBN, MTOT / GBM), 256, gemm_smem>>>(
        xnh, wqkvT, nullptr, nullptr, qkv, fcos, fsin, MTOT, QKVS, DIMV);

    // 3. attention
    attn_mma<<<dim3(SEQ / BQ, BATCH * NHEADS), 256, attn_smem>>>(qkv, ath);

    // 4. h = x + at @ wo
    gemm_hmma<0><<<dim3(DIMV / GBN, MTOT / GBM), 256, gemm_smem>>>(
        ath, woT, x, h, nullptr, nullptr, nullptr, MTOT, DIMV, DIMV);

    // 5. hn = rmsnorm(h)
    rmsnorm_kernel<<<MTOT, 256>>>(h, fnw, xnh);

    // 6. g1 = silu(hn@w1) * (hn@w3)   (interleaved weights, fused)
    gemm_hmma<3><<<dim3(2 * HIDDEN / GBN, MTOT / GBM), 256, gemm_smem>>>(
        xnh, w13i, nullptr, nullptr, g1h, nullptr, nullptr, MTOT, 2 * HIDDEN, DIMV);

    // 7. out = h + g1 @ w2
    gemm_hmma<0><<<dim3(DIMV / GBN, MTOT / GBM), 256, gemm_smem>>>(
        g1h, w2T, h, out, nullptr, nullptr, nullptr, MTOT, DIMV, HIDDEN);
}

// round 9
// speedup vs baseline: 6.9993x; 1.0960x over previous
#include <cuda_runtime.h>
#include <cuda_fp16.h>
#include <math.h>
#include <stdint.h>

#define DIMV    2048
#define NHEADS  16
#define HD      128
#define HIDDEN  8192
#define BATCH   2
#define SEQ     2048
#define MTOT    (BATCH*SEQ)
#define QKVS    (3*DIMV)
#define EPSV    1e-6f

// ---------------- scratch ----------------
__device__ __half g_xnh [MTOT*DIMV];
__device__ __half g_qkv [MTOT*QKVS];
__device__ __half g_ath [MTOT*DIMV];
__device__ float  g_h   [MTOT*DIMV];
__device__ __half g_g1h [MTOT*HIDDEN];
__device__ __half g_wqkvT[3*DIMV*DIMV];
__device__ __half g_woT [DIMV*DIMV];
__device__ __half g_w13i[2*HIDDEN*DIMV];
__device__ __half g_w2T [DIMV*HIDDEN];

__device__ __forceinline__ uint32_t smem_u32(const void* p) {
    uint32_t a;
    asm("{ .reg .u64 t; cvta.to.shared.u64 t, %1; cvt.u32.u64 %0, t; }" : "=r"(a) : "l"(p));
    return a;
}
__device__ __forceinline__ uint32_t h2_to_u32(__half2 h) {
    union { __half2 h2; uint32_t u; } cvt;
    cvt.h2 = h;
    return cvt.u;
}
__device__ __forceinline__ void mma16816(float* c, const uint32_t* a, const uint32_t* b) {
    asm volatile("mma.sync.aligned.m16n8k16.row.col.f32.f16.f16.f32 "
        "{%0,%1,%2,%3}, {%4,%5,%6,%7}, {%8,%9}, {%0,%1,%2,%3};"
        : "+f"(c[0]), "+f"(c[1]), "+f"(c[2]), "+f"(c[3])
        : "r"(a[0]), "r"(a[1]), "r"(a[2]), "r"(a[3]), "r"(b[0]), "r"(b[1]));
}
__device__ __forceinline__ void ldsm_x4(uint32_t* r, uint32_t addr) {
    asm volatile("ldmatrix.sync.aligned.m8n8.x4.shared.b16 {%0,%1,%2,%3}, [%4];"
        : "=r"(r[0]), "=r"(r[1]), "=r"(r[2]), "=r"(r[3]) : "r"(addr));
}
__device__ __forceinline__ void ldsm_x4_t(uint32_t* r, uint32_t addr) {
    asm volatile("ldmatrix.sync.aligned.m8n8.x4.trans.shared.b16 {%0,%1,%2,%3}, [%4];"
        : "=r"(r[0]), "=r"(r[1]), "=r"(r[2]), "=r"(r[3]) : "r"(addr));
}

// ---------------- RMSNorm (fp32 in, half out) ----------------
__global__ __launch_bounds__(256) void rmsnorm_kernel(
    const float* __restrict__ x, const float* __restrict__ w, __half* __restrict__ y)
{
    int row = blockIdx.x;
    const float* xr = x + (size_t)row * DIMV;
    float ss = 0.f;
    for (int i = threadIdx.x * 4; i < DIMV; i += blockDim.x * 4) {
        float4 v = *(const float4*)(xr + i);
        ss += v.x*v.x + v.y*v.y + v.z*v.z + v.w*v.w;
    }
    __shared__ float red[8];
    for (int o = 16; o > 0; o >>= 1) ss += __shfl_down_sync(0xffffffffu, ss, o);
    int warp = threadIdx.x >> 5, lane = threadIdx.x & 31;
    if (lane == 0) red[warp] = ss;
    __syncthreads();
    if (warp == 0) {
        float t = (lane < 8) ? red[lane] : 0.f;
        for (int o = 4; o > 0; o >>= 1) t += __shfl_down_sync(0xffffffffu, t, o);
        if (lane == 0) red[0] = t;
    }
    __syncthreads();
    float r = rsqrtf(red[0] / (float)DIMV + EPSV);
    __half* yr = y + (size_t)row * DIMV;
    for (int i = threadIdx.x * 4; i < DIMV; i += blockDim.x * 4) {
        float4 v = *(const float4*)(xr + i);
        float4 ww = *(const float4*)(w + i);
        *(__half2*)(yr + i)     = __floats2half2_rn(v.x * r * ww.x, v.y * r * ww.y);
        *(__half2*)(yr + i + 2) = __floats2half2_rn(v.z * r * ww.z, v.w * r * ww.w);
    }
}

// ---------------- transpose + fp32->half, 64x32 tiles, half2 stores ----------------
__global__ __launch_bounds__(256) void transpose_h_kernel(
    const float* __restrict__ src, __half* __restrict__ dst, int R, int C,
    int istride, int ioff)
{
    __shared__ float t[64][33];
    int bx = blockIdx.x * 32, by = blockIdx.y * 64;
    int tx = threadIdx.x & 31, ty = threadIdx.x >> 5;   // 32 x 8
    #pragma unroll
    for (int i = 0; i < 8; i++)
        t[i * 8 + ty][tx] = src[(size_t)(by + i * 8 + ty) * C + bx + tx];
    __syncthreads();
    #pragma unroll
    for (int i = 0; i < 4; i++) {
        int j = i * 8 + ty;
        __half2 v = __floats2half2_rn(t[2 * tx][j], t[2 * tx + 1][j]);
        *(__half2*)(dst + (size_t)(istride * (bx + j) + ioff) * R + by + 2 * tx) = v;
    }
}

// ---------------- HMMA fp16 GEMM, ring-3 pipeline, fused epilogues ----------------
// MODE 0: fp32 out (+R residual);  MODE 2: half out + RoPE for n<2*DIMV;
// MODE 3: swiglu (B col-interleaved w1/w3), half out at col n/2
#define GBM 128
#define GBN 128
#define GBK 32
#define APAD 40
#define TILE_H (128*APAD)

template <int MODE>
__global__ __launch_bounds__(256) void gemm_hmma(
    const __half* __restrict__ A, const __half* __restrict__ Bt,
    const float* __restrict__ R, float* __restrict__ Cf, __half* __restrict__ Ch,
    const float* __restrict__ cs, const float* __restrict__ sn,
    int Mn, int Nn, int Kn)
{
    extern __shared__ __half hs[];
    __half* As = hs;                 // ring of 3
    __half* Bs = hs + 3 * TILE_H;    // ring of 3
    const int tid = threadIdx.x;
    const int lane = tid & 31, wid = tid >> 5;
    const int wm = wid >> 2, wn = wid & 3;
    const int bm = blockIdx.y * GBM, bn = blockIdx.x * GBN;

    float acc[4][4][4];
    #pragma unroll
    for (int i = 0; i < 4; i++)
        #pragma unroll
        for (int j = 0; j < 4; j++)
            #pragma unroll
            for (int q = 0; q < 4; q++) acc[i][j][q] = 0.f;

    const __half* Ag = A + (size_t)bm * Kn;
    const __half* Bg = Bt + (size_t)bn * Kn;
    const int r0 = tid >> 2, c0 = (tid & 3) * 8;
    const int r1 = (tid + 256) >> 2;
    const uint32_t sA0 = smem_u32(As), sB0 = smem_u32(Bs);
    const int NC = Kn / GBK;

#define ISSUE(stage, c)                                                          \
    {                                                                            \
        int kb = (c) * GBK;                                                      \
        uint32_t sA = sA0 + (stage) * TILE_H * 2;                                \
        uint32_t sB = sB0 + (stage) * TILE_H * 2;                                \
        asm volatile("cp.async.cg.shared.global [%0], [%1], 16;"                 \
                     :: "r"(sA + (r0 * APAD + c0) * 2), "l"(Ag + (size_t)r0 * Kn + kb + c0)); \
        asm volatile("cp.async.cg.shared.global [%0], [%1], 16;"                 \
                     :: "r"(sB + (r0 * APAD + c0) * 2), "l"(Bg + (size_t)r0 * Kn + kb + c0)); \
        asm volatile("cp.async.cg.shared.global [%0], [%1], 16;"                 \
                     :: "r"(sA + (r1 * APAD + c0) * 2), "l"(Ag + (size_t)r1 * Kn + kb + c0)); \
        asm volatile("cp.async.cg.shared.global [%0], [%1], 16;"                 \
                     :: "r"(sB + (r1 * APAD + c0) * 2), "l"(Bg + (size_t)r1 * Kn + kb + c0)); \
        asm volatile("cp.async.commit_group;" ::: "memory");                     \
    }

    ISSUE(0, 0);
    ISSUE(1, 1);

    for (int c = 0; c < NC; c++) {
        const int s = c - (c / 3) * 3;   // c % 3
        if (c + 1 < NC) asm volatile("cp.async.wait_group 1;" ::: "memory");
        else            asm volatile("cp.async.wait_group 0;" ::: "memory");
        __syncthreads();
        // issue chunk c+2 into stage (c+2)%3: that stage was last read at
        // iteration c-1; the barrier above proves all warps are past it.
        if (c + 2 < NC) {
            int s2 = (c + 2) - ((c + 2) / 3) * 3;
            ISSUE(s2, c + 2);
        }
        const uint32_t aBase = sA0 + s * TILE_H * 2;
        const uint32_t bBase = sB0 + s * TILE_H * 2;
        #pragma unroll
        for (int kk = 0; kk < 2; kk++) {
            uint32_t afr[4][4], bfr[4][2];
            #pragma unroll
            for (int mi = 0; mi < 4; mi++) {
                int row = wm * 64 + mi * 16 + (lane & 15);
                int col = kk * 16 + (lane >> 4) * 8;
                ldsm_x4(afr[mi], aBase + (row * APAD + col) * 2);
            }
            #pragma unroll
            for (int jp = 0; jp < 2; jp++) {
                uint32_t t4[4];
                int row = wn * 32 + (jp * 2 + (lane >> 4)) * 8 + (lane & 7);
                int col = kk * 16 + ((lane >> 3) & 1) * 8;
                ldsm_x4(t4, bBase + (row * APAD + col) * 2);
                bfr[jp*2][0] = t4[0]; bfr[jp*2][1] = t4[1];
                bfr[jp*2+1][0] = t4[2]; bfr[jp*2+1][1] = t4[3];
            }
            #pragma unroll
            for (int mi = 0; mi < 4; mi++)
                #pragma unroll
                for (int ni = 0; ni < 4; ni++)
                    mma16816(acc[mi][ni], afr[mi], bfr[ni]);
        }
    }
#undef ISSUE

    #pragma unroll
    for (int mi = 0; mi < 4; mi++) {
        int mrow0 = bm + wm * 64 + mi * 16 + (lane >> 2);
        #pragma unroll
        for (int hh = 0; hh < 2; hh++) {
            int m = mrow0 + hh * 8;
            int nb = bn + wn * 32 + 2 * (lane & 3);
            #pragma unroll
            for (int ni = 0; ni < 4; ni++) {
                int n = nb + ni * 8;
                float va = acc[mi][ni][hh * 2 + 0], vb = acc[mi][ni][hh * 2 + 1];
                if (MODE == 0) {
                    size_t off = (size_t)m * Nn + n;
                    if (R) {
                        float2 rv = *(const float2*)(R + off);
                        va += rv.x; vb += rv.y;
                    }
                    *(float2*)(Cf + off) = make_float2(va, vb);
                } else if (MODE == 2) {
                    size_t off = (size_t)m * Nn + n;
                    if (n < 2 * DIMV) {
                        int i2 = (n & (HD - 1)) >> 1;
                        int sidx = m & (SEQ - 1);
                        float cc = cs[sidx * (HD / 2) + i2];
                        float si = sn[sidx * (HD / 2) + i2];
                        float ra = va * cc - vb * si;
                        float rb = va * si + vb * cc;
                        *(__half2*)(Ch + off) = __floats2half2_rn(ra, rb);
                    } else {
                        *(__half2*)(Ch + off) = __floats2half2_rn(va, vb);
                    }
                } else {  // swiglu
                    float g = va / (1.f + __expf(-va)) * vb;
                    Ch[(size_t)m * (Nn >> 1) + (n >> 1)] = __float2half(g);
                }
            }
        }
    }
}

// ---------------- Flash attention, fp16 mma, causal, ring-3 KV pipeline ----------------
#define BQ  128
#define BKV 64
#define KVS 136

__global__ __launch_bounds__(256) void attn_mma(
    const __half* __restrict__ QKV, __half* __restrict__ O)
{
    extern __shared__ __half kvsm[];
    __half* Ks = kvsm;                     // ring of 3
    __half* Vs = kvsm + 3 * BKV * KVS;     // ring of 3
    const int tid = threadIdx.x, lane = tid & 31, w = tid >> 5;
    const int qt = blockIdx.x, bh = blockIdx.y;
    const int b = bh >> 4, h = bh & 15;
    const int q0 = qt * BQ;
    const int r = lane >> 2, cq = (lane & 3) * 2;
    const float scale = 0.08838834764831845f;

    uint32_t qf[8][4];
    {
        const __half* Qg  = QKV + (size_t)(b * SEQ + q0 + w * 16 + r) * QKVS + h * HD;
        const __half* Qg8 = Qg + 8 * (size_t)QKVS;
        #pragma unroll
        for (int kk = 0; kk < 8; kk++) {
            qf[kk][0] = *(const uint32_t*)(Qg  + kk * 16 + cq);
            qf[kk][1] = *(const uint32_t*)(Qg8 + kk * 16 + cq);
            qf[kk][2] = *(const uint32_t*)(Qg  + kk * 16 + 8 + cq);
            qf[kk][3] = *(const uint32_t*)(Qg8 + kk * 16 + 8 + cq);
        }
    }

    float oacc[16][4];
    #pragma unroll
    for (int j = 0; j < 16; j++)
        #pragma unroll
        for (int q = 0; q < 4; q++) oacc[j][q] = 0.f;
    float m0 = -1e30f, m1 = -1e30f, l0 = 0.f, l1 = 0.f;

    const uint32_t sKs = smem_u32(Ks), sVs = smem_u32(Vs);
    const __half* Kg = QKV + (size_t)(b * SEQ) * QKVS + DIMV + h * HD;
    const __half* Vg = QKV + (size_t)(b * SEQ) * QKVS + 2 * DIMV + h * HD;
    const int nkt = qt * 2 + 2;

#define KV_ISSUE(stage, kt)                                                        \
    {                                                                              \
        _Pragma("unroll")                                                          \
        for (int ii = 0; ii < 4; ii++) {                                           \
            int idx = tid + ii * 256;                                              \
            int rr = idx >> 4, cc = (idx & 15) * 8;                                \
            uint32_t doff = (uint32_t)(((stage) * BKV + rr) * KVS + cc) * 2;       \
            asm volatile("cp.async.cg.shared.global [%0], [%1], 16;"               \
                :: "r"(sKs + doff), "l"(Kg + (size_t)((kt) * BKV + rr) * QKVS + cc)); \
            asm volatile("cp.async.cg.shared.global [%0], [%1], 16;"               \
                :: "r"(sVs + doff), "l"(Vg + (size_t)((kt) * BKV + rr) * QKVS + cc)); \
        }                                                                          \
        asm volatile("cp.async.commit_group;" ::: "memory");                       \
    }

    KV_ISSUE(0, 0);
    if (nkt > 1) KV_ISSUE(1, 1);

    for (int kt = 0; kt < nkt; kt++) {
        const int s = kt - (kt / 3) * 3;
        if (kt + 1 < nkt) asm volatile("cp.async.wait_group 1;" ::: "memory");
        else              asm volatile("cp.async.wait_group 0;" ::: "memory");
        __syncthreads();
        if (kt + 2 < nkt) {
            int s2 = (kt + 2) - ((kt + 2) / 3) * 3;
            KV_ISSUE(s2, kt + 2);
        }
        const uint32_t kb = sKs + (uint32_t)(s * BKV * KVS) * 2;
        const uint32_t vb = sVs + (uint32_t)(s * BKV * KVS) * 2;

        float sa[8][4];
        #pragma unroll
        for (int j = 0; j < 8; j++)
            #pragma unroll
            for (int q = 0; q < 4; q++) sa[j][q] = 0.f;
        #pragma unroll
        for (int kk = 0; kk < 8; kk++) {
            uint32_t kf[8][2];
            #pragma unroll
            for (int jp = 0; jp < 4; jp++) {
                uint32_t t4[4];
                int nt = jp * 2 + (lane >> 4);
                uint32_t addr = kb + (uint32_t)((nt * 8 + (lane & 7)) * KVS
                                + kk * 16 + ((lane >> 3) & 1) * 8) * 2;
                ldsm_x4(t4, addr);
                kf[jp*2][0] = t4[0]; kf[jp*2][1] = t4[1];
                kf[jp*2+1][0] = t4[2]; kf[jp*2+1][1] = t4[3];
            }
            #pragma unroll
            for (int j = 0; j < 8; j++)
                mma16816(sa[j], qf[kk], kf[j]);
        }

        const int row0 = q0 + w * 16 + r, row1 = row0 + 8;
        const bool need_mask = (kt * BKV + BKV - 1) > row0 || (kt * BKV + BKV - 1) > row1;
        float mx0 = -1e30f, mx1 = -1e30f;
        #pragma unroll
        for (int j = 0; j < 8; j++) {
            int col = kt * BKV + j * 8 + cq;
            sa[j][0] *= scale; sa[j][1] *= scale;
            sa[j][2] *= scale; sa[j][3] *= scale;
            if (need_mask) {
                if (col     > row0) sa[j][0] = -1e30f;
                if (col + 1 > row0) sa[j][1] = -1e30f;
                if (col     > row1) sa[j][2] = -1e30f;
                if (col + 1 > row1) sa[j][3] = -1e30f;
            }
            mx0 = fmaxf(mx0, fmaxf(sa[j][0], sa[j][1]));
            mx1 = fmaxf(mx1, fmaxf(sa[j][2], sa[j][3]));
        }
        mx0 = fmaxf(mx0, __shfl_xor_sync(0xffffffffu, mx0, 1));
        mx0 = fmaxf(mx0, __shfl_xor_sync(0xffffffffu, mx0, 2));
        mx1 = fmaxf(mx1, __shfl_xor_sync(0xffffffffu, mx1, 1));
        mx1 = fmaxf(mx1, __shfl_xor_sync(0xffffffffu, mx1, 2));
        float mn0 = fmaxf(m0, mx0), mn1 = fmaxf(m1, mx1);
        float a0 = __expf(m0 - mn0), a1 = __expf(m1 - mn1);
        float s0 = 0.f, s1 = 0.f;
        uint32_t ph[8][2];
        #pragma unroll
        for (int j = 0; j < 8; j++) {
            float p00 = __expf(sa[j][0] - mn0);
            float p01 = __expf(sa[j][1] - mn0);
            float p10 = __expf(sa[j][2] - mn1);
            float p11 = __expf(sa[j][3] - mn1);
            s0 += p00 + p01; s1 += p10 + p11;
            ph[j][0] = h2_to_u32(__floats2half2_rn(p00, p01));
            ph[j][1] = h2_to_u32(__floats2half2_rn(p10, p11));
        }
        s0 += __shfl_xor_sync(0xffffffffu, s0, 1);
        s0 += __shfl_xor_sync(0xffffffffu, s0, 2);
        s1 += __shfl_xor_sync(0xffffffffu, s1, 1);
        s1 += __shfl_xor_sync(0xffffffffu, s1, 2);
        l0 = l0 * a0 + s0; l1 = l1 * a1 + s1;
        m0 = mn0; m1 = mn1;
        #pragma unroll
        for (int j = 0; j < 16; j++) {
            oacc[j][0] *= a0; oacc[j][1] *= a0;
            oacc[j][2] *= a1; oacc[j][3] *= a1;
        }

        #pragma unroll
        for (int kk2 = 0; kk2 < 4; kk2++) {
            uint32_t pa[4] = { ph[kk2*2][0], ph[kk2*2][1], ph[kk2*2+1][0], ph[kk2*2+1][1] };
            #pragma unroll
            for (int jp = 0; jp < 8; jp++) {
                uint32_t vt[4];
                uint32_t addr = vb + (uint32_t)((kk2 * 16 + (lane & 15)) * KVS
                                + (jp * 2 + (lane >> 4)) * 8) * 2;
                ldsm_x4_t(vt, addr);
                mma16816(oacc[jp*2],     pa, &vt[0]);
                mma16816(oacc[jp*2 + 1], pa, &vt[2]);
            }
        }
    }
#undef KV_ISSUE

    float i0 = 1.f / l0, i1 = 1.f / l1;
    __half* Og  = O + (size_t)(b * SEQ + q0 + w * 16 + r) * DIMV + h * HD + cq;
    __half* Og8 = Og + 8 * (size_t)DIMV;
    #pragma unroll
    for (int j = 0; j < 16; j++) {
        *(__half2*)(Og  + j * 8) = __floats2half2_rn(oacc[j][0] * i0, oacc[j][1] * i0);
        *(__half2*)(Og8 + j * 8) = __floats2half2_rn(oacc[j][2] * i1, oacc[j][3] * i1);
    }
}

// ---------------- launch ----------------
extern "C" void kernel_launch(void* const* d_in, const int* in_sizes, int n_in,
                              void* d_out, int out_size)
{
    const float* x    = (const float*)d_in[0];
    const float* fcos = (const float*)d_in[1];
    const float* fsin = (const float*)d_in[2];
    const float* wq   = (const float*)d_in[4];
    const float* wk   = (const float*)d_in[5];
    const float* wv   = (const float*)d_in[6];
    const float* wo   = (const float*)d_in[7];
    const float* w1   = (const float*)d_in[8];
    const float* w2   = (const float*)d_in[9];
    const float* w3   = (const float*)d_in[10];
    const float* anw  = (const float*)d_in[11];
    const float* fnw  = (const float*)d_in[12];
    float* out = (float*)d_out;

    __half *xnh, *qkv, *ath, *g1h;
    float *h;
    __half *wqkvT, *woT, *w13i, *w2T;
    cudaGetSymbolAddress((void**)&xnh,   g_xnh);
    cudaGetSymbolAddress((void**)&qkv,   g_qkv);
    cudaGetSymbolAddress((void**)&ath,   g_ath);
    cudaGetSymbolAddress((void**)&h,     g_h);
    cudaGetSymbolAddress((void**)&g1h,   g_g1h);
    cudaGetSymbolAddress((void**)&wqkvT, g_wqkvT);
    cudaGetSymbolAddress((void**)&woT,   g_woT);
    cudaGetSymbolAddress((void**)&w13i,  g_w13i);
    cudaGetSymbolAddress((void**)&w2T,   g_w2T);

    const int gemm_smem = 6 * TILE_H * (int)sizeof(__half);   // 61440
    cudaFuncSetAttribute(gemm_hmma<0>, cudaFuncAttributeMaxDynamicSharedMemorySize, gemm_smem);
    cudaFuncSetAttribute(gemm_hmma<2>, cudaFuncAttributeMaxDynamicSharedMemorySize, gemm_smem);
    cudaFuncSetAttribute(gemm_hmma<3>, cudaFuncAttributeMaxDynamicSharedMemorySize, gemm_smem);
    const int attn_smem = 6 * BKV * KVS * (int)sizeof(__half);  // 104448
    cudaFuncSetAttribute(attn_mma, cudaFuncAttributeMaxDynamicSharedMemorySize, attn_smem);

    // 0. weights -> half, transposed / packed / interleaved
    {
        dim3 blk(256);
        transpose_h_kernel<<<dim3(DIMV/32, DIMV/64), blk>>>(wq, wqkvT,               DIMV, DIMV, 1, 0);
        transpose_h_kernel<<<dim3(DIMV/32, DIMV/64), blk>>>(wk, wqkvT + DIMV*DIMV,   DIMV, DIMV, 1, 0);
        transpose_h_kernel<<<dim3(DIMV/32, DIMV/64), blk>>>(wv, wqkvT + 2*DIMV*DIMV, DIMV, DIMV, 1, 0);
        transpose_h_kernel<<<dim3(DIMV/32, DIMV/64), blk>>>(wo, woT, DIMV, DIMV, 1, 0);
        transpose_h_kernel<<<dim3(HIDDEN/32, DIMV/64), blk>>>(w1, w13i, DIMV, HIDDEN, 2, 0);
        transpose_h_kernel<<<dim3(HIDDEN/32, DIMV/64), blk>>>(w3, w13i, DIMV, HIDDEN, 2, 1);
        transpose_h_kernel<<<dim3(DIMV/32, HIDDEN/64), blk>>>(w2, w2T, HIDDEN, DIMV, 1, 0);
    }

    // 1. xn = rmsnorm(x)
    rmsnorm_kernel<<<MTOT, 256>>>(x, anw, xnh);

    // 2. qkv = xn @ [wq|wk|wv], RoPE fused
    gemm_hmma<2><<<dim3(QKVS / GBN, MTOT / GBM), 256, gemm_smem>>>(
        xnh, wqkvT, nullptr, nullptr, qkv, fcos, fsin, MTOT, QKVS, DIMV);

    // 3. attention
    attn_mma<<<dim3(SEQ / BQ, BATCH * NHEADS), 256, attn_smem>>>(qkv, ath);

    // 4. h = x + at @ wo
    gemm_hmma<0><<<dim3(DIMV / GBN, MTOT / GBM), 256, gemm_smem>>>(
        ath, woT, x, h, nullptr, nullptr, nullptr, MTOT, DIMV, DIMV);

    // 5. hn = rmsnorm(h)
    rmsnorm_kernel<<<MTOT, 256>>>(h, fnw, xnh);

    // 6. g1 = silu(hn@w1) * (hn@w3)
    gemm_hmma<3><<<dim3(2 * HIDDEN / GBN, MTOT / GBM), 256, gemm_smem>>>(
        xnh, w13i, nullptr, nullptr, g1h, nullptr, nullptr, MTOT, 2 * HIDDEN, DIMV);

    // 7. out = h + g1 @ w2
    gemm_hmma<0><<<dim3(DIMV / GBN, MTOT / GBM), 256, gemm_smem>>>(
        g1h, w2T, h, out, nullptr, nullptr, nullptr, MTOT, DIMV, HIDDEN);
}